// round 14
// baseline (speedup 1.0000x reference)
#include <cuda_runtime.h>
#include <cuda_fp16.h>
#include <math.h>
#include <stdint.h>

#define S_LEN   2048
#define D_MODEL 4096
#define NQH     32
#define NKVH    8
#define HD      128
#define KV_DIM  1024
#define SCALE_F 0.08838834764831845f   // 128^-0.5

// fp16 planes
__device__ __half g_hh[S_LEN * D_MODEL];   // hidden fp16
__device__ __half g_wqh[D_MODEL * D_MODEL];
__device__ __half g_wkh[KV_DIM * D_MODEL];
__device__ __half g_wvh[KV_DIM * D_MODEL];
__device__ __half g_woh[D_MODEL * D_MODEL];
__device__ __half g_ah[S_LEN * D_MODEL];   // attn out fp16
// fp16 flash inputs (written by fused qkv epilogues)
__device__ __half g_qh[S_LEN * D_MODEL];   // q (post norm+rope)
__device__ __half g_kh[S_LEN * KV_DIM];    // k (post norm+rope)
__device__ __half g_vt[KV_DIM * S_LEN];    // v transposed [kv*128+d][s]

// ---------------------------------------------------------------------------
// helpers
// ---------------------------------------------------------------------------
__device__ __forceinline__ void mma_f16(float (&d)[4],
    uint32_t a0, uint32_t a1, uint32_t a2, uint32_t a3,
    uint32_t b0, uint32_t b1) {
    asm volatile(
        "mma.sync.aligned.m16n8k16.row.col.f32.f16.f16.f32 "
        "{%0,%1,%2,%3}, {%4,%5,%6,%7}, {%8,%9}, {%0,%1,%2,%3};\n"
        : "+f"(d[0]), "+f"(d[1]), "+f"(d[2]), "+f"(d[3])
        : "r"(a0), "r"(a1), "r"(a2), "r"(a3), "r"(b0), "r"(b1));
}

__device__ __forceinline__ void ldsm4(uint32_t (&r)[4], uint32_t addr) {
    asm volatile("ldmatrix.sync.aligned.m8n8.x4.shared.b16 {%0,%1,%2,%3}, [%4];"
        : "=r"(r[0]), "=r"(r[1]), "=r"(r[2]), "=r"(r[3]) : "r"(addr));
}

__device__ __forceinline__ void split2h(float x0, float x1,
                                        __half2& hi, __half2& lo) {
    hi = __floats2half2_rn(x0, x1);
    float2 hf = __half22float2(hi);
    lo = __floats2half2_rn(x0 - hf.x, x1 - hf.y);
}

__device__ __forceinline__ uint32_t h2u(__half2 v) {
    return *reinterpret_cast<uint32_t*>(&v);
}

// ---------------------------------------------------------------------------
// pre-pass: all fp32->fp16 conversions in ONE launch
// ---------------------------------------------------------------------------
#define SEG0 (2 * 1024 * 1024)
#define SEG1 (SEG0 + 4 * 1024 * 1024)
#define SEG2 (SEG1 + 1024 * 1024)
#define SEG3 (SEG2 + 1024 * 1024)
#define SEG4 (SEG3 + 4 * 1024 * 1024)

__global__ __launch_bounds__(256)
void split_all(const float4* __restrict__ hidden, const float4* __restrict__ Wq,
               const float4* __restrict__ Wk, const float4* __restrict__ Wv,
               const float4* __restrict__ Wo)
{
    int stride = gridDim.x * blockDim.x;
    for (int i = blockIdx.x * blockDim.x + threadIdx.x; i < SEG4; i += stride) {
        const float4* src;
        uint2* hi;
        int off;
        if (i < SEG0)      { src = hidden; off = i;        hi = (uint2*)g_hh; }
        else if (i < SEG1) { src = Wq;     off = i - SEG0; hi = (uint2*)g_wqh; }
        else if (i < SEG2) { src = Wk;     off = i - SEG1; hi = (uint2*)g_wkh; }
        else if (i < SEG3) { src = Wv;     off = i - SEG2; hi = (uint2*)g_wvh; }
        else               { src = Wo;     off = i - SEG3; hi = (uint2*)g_woh; }
        float4 v = src[off];
        hi[off] = make_uint2(h2u(__floats2half2_rn(v.x, v.y)),
                             h2u(__floats2half2_rn(v.z, v.w)));
    }
}

// ---------------------------------------------------------------------------
// fp16 1-term GEMM NT with cp.async + fused epilogues.
// MODE 0: C fp32 (plain).  MODE 1: Q rmsnorm+rope -> g_qh fp16.
// MODE 2: K rmsnorm+rope -> g_kh fp16.  MODE 3: V transpose -> g_vt fp16.
// CTA tile 128x128 (= one head per CTA for modes 1-3), BK=32, 256 threads,
// 8 warps (4m x 2n), warp tile 32x64. 4-stage cp.async; 2 CTAs/SM.
// ---------------------------------------------------------------------------
#define LDBH   40
#define AP_H   (128 * LDBH)
#define STG_B  (2 * AP_H * 2)            // 20480 B per stage
#define HGEMM_SMEM 81920                 // 4 stages; also >= 128*132*4 staging

#define TSLD 132

template <int MODE>
__device__ __forceinline__ void hgemm_body(const __half* __restrict__ Ah,
                                           const __half* __restrict__ Bh,
                                           float* __restrict__ C, int N, int K,
                                           int bx, int by,
                                           const float* __restrict__ cosb,
                                           const float* __restrict__ sinb,
                                           const float* __restrict__ w)
{
    extern __shared__ char smc[];
    const uint32_t smem_u32 = (uint32_t)__cvta_generic_to_shared(smc);

    const int tid  = threadIdx.x;
    const int warp = tid >> 5;
    const int lane = tid & 31;
    const int g    = lane >> 2;
    const int t    = lane & 3;
    const int wm   = (warp & 3) * 32;
    const int wn   = (warp >> 2) * 64;

    uint32_t dst_off[4];
    const __half* src[4];
#pragma unroll
    for (int j = 0; j < 4; j++) {
        int cid = tid + j * 256;
        if (cid < 512) {
            int r = cid >> 2, c = cid & 3;
            dst_off[j] = (uint32_t)(r * LDBH + c * 8) * 2;
            src[j] = Ah + (size_t)(by * 128 + r) * K + c * 8;
        } else {
            int b = cid - 512;
            int r = b >> 2, c = b & 3;
            dst_off[j] = (uint32_t)(AP_H + r * LDBH + c * 8) * 2;
            src[j] = Bh + (size_t)(bx * 128 + r) * K + c * 8;
        }
    }

    const int lane8 = lane & 7;
    const uint32_t a_off = (uint32_t)(((wm + lane8 + ((lane >> 3) & 1) * 8) * LDBH
                                      + (lane >> 4) * 8) * 2);
    const uint32_t b_off = (uint32_t)((AP_H + (wn + lane8 + (lane >> 4) * 8) * LDBH
                                      + ((lane >> 3) & 1) * 8) * 2);

    float acc[2][8][4];
#pragma unroll
    for (int mt = 0; mt < 2; mt++)
#pragma unroll
        for (int nt = 0; nt < 8; nt++)
#pragma unroll
            for (int c = 0; c < 4; c++) acc[mt][nt][c] = 0.0f;

    const int nk = K / 32;

#define CP_ISSUE(KT)                                                           \
    {                                                                          \
        uint32_t sb_ = smem_u32 + (uint32_t)(((KT) & 3) * STG_B);              \
        _Pragma("unroll")                                                      \
        for (int j = 0; j < 4; j++) {                                          \
            asm volatile("cp.async.cg.shared.global [%0], [%1], 16;"           \
                :: "r"(sb_ + dst_off[j]), "l"(src[j] + (KT) * 32) : "memory"); \
        }                                                                      \
    }
#define CP_COMMIT() asm volatile("cp.async.commit_group;" ::: "memory")

    CP_ISSUE(0); CP_COMMIT();
    CP_ISSUE(1); CP_COMMIT();
    CP_ISSUE(2); CP_COMMIT();

    for (int kt = 0; kt < nk; kt++) {
        asm volatile("cp.async.wait_group 2;" ::: "memory");
        __syncthreads();
        if (kt + 3 < nk) { CP_ISSUE(kt + 3); }
        CP_COMMIT();

        const uint32_t sb = smem_u32 + (uint32_t)((kt & 3) * STG_B);

#pragma unroll
        for (int k16 = 0; k16 < 2; k16++) {
            uint32_t ah[2][4];
            ldsm4(ah[0], sb + a_off + k16 * 32);
            ldsm4(ah[1], sb + a_off + 16 * LDBH * 2 + k16 * 32);

#pragma unroll
            for (int jh = 0; jh < 2; jh++) {
                uint32_t bh[2][4];
#pragma unroll
                for (int jj = 0; jj < 2; jj++) {
                    int j = jh * 2 + jj;
                    ldsm4(bh[jj], sb + b_off + j * 16 * LDBH * 2 + k16 * 32);
                }
#pragma unroll
                for (int mt = 0; mt < 2; mt++)
#pragma unroll
                    for (int jj = 0; jj < 2; jj++) {
                        int nt = (jh * 2 + jj) * 2;
                        mma_f16(acc[mt][nt], ah[mt][0], ah[mt][1], ah[mt][2],
                                ah[mt][3], bh[jj][0], bh[jj][1]);
                        mma_f16(acc[mt][nt + 1], ah[mt][0], ah[mt][1], ah[mt][2],
                                ah[mt][3], bh[jj][2], bh[jj][3]);
                    }
            }
        }
    }

    if (MODE == 0) {
#pragma unroll
        for (int mt = 0; mt < 2; mt++) {
            int r0 = by * 128 + wm + mt * 16 + g;
#pragma unroll
            for (int nt = 0; nt < 8; nt++) {
                int c0 = bx * 128 + wn + nt * 8 + 2 * t;
                *(float2*)&C[(size_t)r0 * N + c0] =
                    make_float2(acc[mt][nt][0], acc[mt][nt][1]);
                *(float2*)&C[(size_t)(r0 + 8) * N + c0] =
                    make_float2(acc[mt][nt][2], acc[mt][nt][3]);
            }
        }
        return;
    }

    // ---- fused epilogues: stage acc tile to smem fp32 (reuse pipe smem) ----
    asm volatile("cp.async.wait_all;" ::: "memory");
    __syncthreads();                      // all warps done with pipe buffers
    float* TS = (float*)smc;              // [128][TSLD]
#pragma unroll
    for (int mt = 0; mt < 2; mt++) {
#pragma unroll
        for (int nt = 0; nt < 8; nt++) {
            int r = wm + mt * 16 + g;
            int c = wn + nt * 8 + 2 * t;
            *(float2*)&TS[r * TSLD + c] =
                make_float2(acc[mt][nt][0], acc[mt][nt][1]);
            *(float2*)&TS[(r + 8) * TSLD + c] =
                make_float2(acc[mt][nt][2], acc[mt][nt][3]);
        }
    }
    __syncthreads();

    const int q0 = by * 128;

    if (MODE == 1 || MODE == 2) {
        // per-row RMSNorm (fp32) + RoPE, write fp16. 4 threads/row, 2 passes.
        for (int p = 0; p < 2; p++) {
            int r = p * 64 + (tid >> 2);
            int q = tid & 3;
            float v[32];
            float ss = 0.0f;
#pragma unroll
            for (int j = 0; j < 32; j++) {
                v[j] = TS[r * TSLD + q * 32 + j];
                ss += v[j] * v[j];
            }
            ss += __shfl_xor_sync(0xffffffffu, ss, 1);
            ss += __shfl_xor_sync(0xffffffffu, ss, 2);
            float inv = rsqrtf(ss * (1.0f / 128.0f) + 1e-6f);
#pragma unroll
            for (int j = 0; j < 32; j++) v[j] = w[q * 32 + j] * v[j] * inv;
#pragma unroll
            for (int j = 0; j < 32; j++) TS[r * TSLD + q * 32 + j] = v[j];
            __syncthreads();

            int s = q0 + r;
            __half o16[32];
            if (q < 2) {
#pragma unroll
                for (int j = 0; j < 32; j++) {
                    int x = q * 32 + j;
                    float pr = TS[r * TSLD + x + 64];
                    o16[j] = __float2half_rn(v[j] * cosb[s * 64 + x] -
                                             pr * sinb[s * 64 + x]);
                }
            } else {
#pragma unroll
                for (int j = 0; j < 32; j++) {
                    int x = q * 32 + j;
                    int xp = x - 64;
                    float pr = TS[r * TSLD + xp];
                    o16[j] = __float2half_rn(v[j] * cosb[s * 64 + xp] +
                                             pr * sinb[s * 64 + xp]);
                }
            }
            __half* dst = (MODE == 1)
                ? g_qh + (size_t)s * D_MODEL + bx * 128 + q * 32
                : g_kh + (size_t)s * KV_DIM + bx * 128 + q * 32;
#pragma unroll
            for (int j = 0; j < 32; j += 2)
                *(__half2*)(dst + j) = __halves2half2(o16[j], o16[j + 1]);
            __syncthreads();   // rows disjoint across passes; orders TS reuse
        }
    } else {
        // MODE 3: V transpose -> g_vt fp16 [bx*128+d][s]
        int d = tid >> 1;
        int sh = tid & 1;
        __half o16[64];
#pragma unroll
        for (int j = 0; j < 64; j++)
            o16[j] = __float2half_rn(TS[(sh * 64 + j) * TSLD + d]);
        __half* dst = g_vt + (size_t)(bx * 128 + d) * S_LEN + q0 + sh * 64;
#pragma unroll
        for (int j = 0; j < 64; j += 2)
            *(__half2*)(dst + j) = __halves2half2(o16[j], o16[j + 1]);
    }
#undef CP_ISSUE
#undef CP_COMMIT
}

// merged Q/K/V projection with fused epilogues: 768 CTAs
__global__ __launch_bounds__(256, 2)
void hgemm_qkv(const float* __restrict__ cosb, const float* __restrict__ sinb,
               const float* __restrict__ qw, const float* __restrict__ kw)
{
    int b = blockIdx.x;
    if (b < 512)
        hgemm_body<1>(g_hh, g_wqh, nullptr, 0, 4096, b & 31, b >> 5, cosb, sinb, qw);
    else if (b < 640) {
        int i = b - 512;
        hgemm_body<2>(g_hh, g_wkh, nullptr, 0, 4096, i & 7, i >> 3, cosb, sinb, kw);
    } else {
        int i = b - 640;
        hgemm_body<3>(g_hh, g_wvh, nullptr, 0, 4096, i & 7, i >> 3, nullptr, nullptr, nullptr);
    }
}

__global__ __launch_bounds__(256, 2)
void hgemm_o(float* __restrict__ out)
{
    hgemm_body<0>(g_ah, g_woh, out, 4096, 4096, blockIdx.x, blockIdx.y,
                  nullptr, nullptr, nullptr);
}

// ---------------------------------------------------------------------------
// Tensor-core flash attention (unchanged from R13): Q single fp16, 4-stage
// cp.async KV pipeline. QK^T fp16 1-term; P.V fp16 2-term; fp16 epilogue.
// ---------------------------------------------------------------------------
#define OFF_QH   0
#define OFF_FKV  17408
#define FKVBUF   17920
#define FLASH_SMEM_TC ((OFF_FKV + 4 * FKVBUF) * 2)   // 178176 B

__global__ __launch_bounds__(256, 1)
void flash_attn_tc()
{
    extern __shared__ __half smh[];

    const int qt  = 15 - blockIdx.x;
    const int h   = blockIdx.y;
    const int q0  = qt * 128;
    const int kvh = h >> 2;
    const int tid  = threadIdx.x;
    const int warp = tid >> 5;
    const int lane = tid & 31;
    const int g = lane >> 2;
    const int t = lane & 3;

    const uint32_t sbase = (uint32_t)__cvta_generic_to_shared(smh);

#define CP16(DST, SRC)                                                         \
    asm volatile("cp.async.cg.shared.global [%0], [%1], 16;"                   \
                 :: "r"(DST), "l"(SRC) : "memory")
#define CP_COMMIT() asm volatile("cp.async.commit_group;" ::: "memory")

#define LOAD_KV(KT, BUF)                                                       \
    {                                                                          \
        const uint32_t kb_ = sbase + (uint32_t)(OFF_FKV + (BUF) * FKVBUF) * 2; \
        const int k0_ = (KT) * 64;                                             \
        _Pragma("unroll")                                                      \
        for (int j = 0; j < 8; j++) {                                          \
            int cid = tid + j * 256;                                           \
            if (cid < 1024) {                                                  \
                int r = cid >> 4, c = cid & 15;                                \
                CP16(kb_ + (uint32_t)(r * 136 + c * 8) * 2,                    \
                     g_kh + (size_t)(k0_ + r) * KV_DIM + kvh * HD + c * 8);    \
            } else {                                                           \
                int b = cid - 1024;                                            \
                int r = b >> 3, c = b & 7;                                     \
                CP16(kb_ + (uint32_t)(8704 + r * 72 + c * 8) * 2,              \
                     g_vt + (size_t)(kvh * HD + r) * S_LEN + k0_ + c * 8);     \
            }                                                                  \
        }                                                                      \
    }

    const int wrow = q0 + warp * 16;
    const int nkt  = 2 * qt + 2;

#pragma unroll
    for (int j = 0; j < 8; j++) {
        int cid = tid + j * 256;
        int r = cid >> 4, c = cid & 15;
        CP16(sbase + (uint32_t)(OFF_QH + r * 136 + c * 8) * 2,
             g_qh + (size_t)(q0 + r) * D_MODEL + h * HD + c * 8);
    }
    LOAD_KV(0, 0);
    CP_COMMIT();
    if (1 < nkt) LOAD_KV(1, 1);
    CP_COMMIT();
    if (2 < nkt) LOAD_KV(2, 2);
    CP_COMMIT();

    float o[16][4];
#pragma unroll
    for (int nt = 0; nt < 16; nt++)
#pragma unroll
        for (int j = 0; j < 4; j++) o[nt][j] = 0.0f;
    float m0 = -1e30f, m1 = -1e30f, l0 = 0.0f, l1 = 0.0f;

    const __half* qrh = smh + OFF_QH + (warp * 16 + g) * 136 + 2 * t;

    for (int kt = 0; kt < nkt; kt++) {
        const int k0 = kt * 64;
        asm volatile("cp.async.wait_group 2;" ::: "memory");
        __syncthreads();
        if (kt + 3 < nkt) LOAD_KV(kt + 3, (kt + 3) & 3);
        CP_COMMIT();

        if (k0 > wrow + 15) continue;

        const __half* Kh = smh + OFF_FKV + (kt & 3) * FKVBUF;
        const __half* Vh = Kh + 8704;

        float s[8][4];
#pragma unroll
        for (int nt = 0; nt < 8; nt++)
#pragma unroll
            for (int j = 0; j < 4; j++) s[nt][j] = 0.0f;

#pragma unroll
        for (int c = 0; c < 8; c++) {
            uint32_t ah0 = *(const uint32_t*)(qrh + c * 16);
            uint32_t ah1 = *(const uint32_t*)(qrh + 8 * 136 + c * 16);
            uint32_t ah2 = *(const uint32_t*)(qrh + c * 16 + 8);
            uint32_t ah3 = *(const uint32_t*)(qrh + 8 * 136 + c * 16 + 8);
#pragma unroll
            for (int nt = 0; nt < 8; nt++) {
                const __half* kp = Kh + (nt * 8 + g) * 136 + c * 16 + 2 * t;
                uint32_t b0 = *(const uint32_t*)(kp);
                uint32_t b1 = *(const uint32_t*)(kp + 8);
                mma_f16(s[nt], ah0, ah1, ah2, ah3, b0, b1);
            }
        }

        if (k0 + 63 > wrow) {
            int r0 = wrow + g, r1 = r0 + 8;
#pragma unroll
            for (int nt = 0; nt < 8; nt++) {
                int c0 = k0 + nt * 8 + 2 * t;
                s[nt][0] = (c0     > r0) ? -1e30f : s[nt][0] * SCALE_F;
                s[nt][1] = (c0 + 1 > r0) ? -1e30f : s[nt][1] * SCALE_F;
                s[nt][2] = (c0     > r1) ? -1e30f : s[nt][2] * SCALE_F;
                s[nt][3] = (c0 + 1 > r1) ? -1e30f : s[nt][3] * SCALE_F;
            }
        } else {
#pragma unroll
            for (int nt = 0; nt < 8; nt++)
#pragma unroll
                for (int j = 0; j < 4; j++) s[nt][j] *= SCALE_F;
        }

        float mx0 = -1e30f, mx1 = -1e30f;
#pragma unroll
        for (int nt = 0; nt < 8; nt++) {
            mx0 = fmaxf(mx0, fmaxf(s[nt][0], s[nt][1]));
            mx1 = fmaxf(mx1, fmaxf(s[nt][2], s[nt][3]));
        }
        mx0 = fmaxf(mx0, __shfl_xor_sync(0xffffffffu, mx0, 1));
        mx0 = fmaxf(mx0, __shfl_xor_sync(0xffffffffu, mx0, 2));
        mx1 = fmaxf(mx1, __shfl_xor_sync(0xffffffffu, mx1, 1));
        mx1 = fmaxf(mx1, __shfl_xor_sync(0xffffffffu, mx1, 2));

        float mn0 = fmaxf(m0, mx0), mn1 = fmaxf(m1, mx1);
        float a0 = __expf(m0 - mn0), a1 = __expf(m1 - mn1);
        m0 = mn0; m1 = mn1;

        float sum0 = 0.0f, sum1 = 0.0f;
#pragma unroll
        for (int nt = 0; nt < 8; nt++) {
            s[nt][0] = __expf(s[nt][0] - m0);
            s[nt][1] = __expf(s[nt][1] - m0);
            s[nt][2] = __expf(s[nt][2] - m1);
            s[nt][3] = __expf(s[nt][3] - m1);
            sum0 += s[nt][0] + s[nt][1];
            sum1 += s[nt][2] + s[nt][3];
        }
        sum0 += __shfl_xor_sync(0xffffffffu, sum0, 1);
        sum0 += __shfl_xor_sync(0xffffffffu, sum0, 2);
        sum1 += __shfl_xor_sync(0xffffffffu, sum1, 1);
        sum1 += __shfl_xor_sync(0xffffffffu, sum1, 2);
        l0 = l0 * a0 + sum0;
        l1 = l1 * a1 + sum1;

#pragma unroll
        for (int nt = 0; nt < 16; nt++) {
            o[nt][0] *= a0; o[nt][1] *= a0;
            o[nt][2] *= a1; o[nt][3] *= a1;
        }

#pragma unroll
        for (int c = 0; c < 4; c++) {
            __half2 h0, lo0, h1, lo1, h2, lo2, h3, lo3;
            split2h(s[2 * c][0],     s[2 * c][1],     h0, lo0);
            split2h(s[2 * c][2],     s[2 * c][3],     h1, lo1);
            split2h(s[2 * c + 1][0], s[2 * c + 1][1], h2, lo2);
            split2h(s[2 * c + 1][2], s[2 * c + 1][3], h3, lo3);
            uint32_t ph0 = h2u(h0), ph1 = h2u(h1), ph2 = h2u(h2), ph3 = h2u(h3);
            uint32_t pl0 = h2u(lo0), pl1 = h2u(lo1), pl2 = h2u(lo2), pl3 = h2u(lo3);
#pragma unroll
            for (int nt = 0; nt < 16; nt++) {
                const __half* vp = Vh + (nt * 8 + g) * 72 + c * 16 + 2 * t;
                uint32_t vh0 = *(const uint32_t*)(vp);
                uint32_t vh1 = *(const uint32_t*)(vp + 8);
                mma_f16(o[nt], ph0, ph1, ph2, ph3, vh0, vh1);
                mma_f16(o[nt], pl0, pl1, pl2, pl3, vh0, vh1);
            }
        }
    }

    float inv0 = 1.0f / l0, inv1 = 1.0f / l1;
    int row0 = q0 + warp * 16 + g;
#pragma unroll
    for (int nt = 0; nt < 16; nt++) {
        int col = h * HD + nt * 8 + 2 * t;
        *(uint32_t*)&g_ah[(size_t)row0 * D_MODEL + col] =
            h2u(__floats2half2_rn(o[nt][0] * inv0, o[nt][1] * inv0));
        *(uint32_t*)&g_ah[(size_t)(row0 + 8) * D_MODEL + col] =
            h2u(__floats2half2_rn(o[nt][2] * inv1, o[nt][3] * inv1));
    }
#undef LOAD_KV
#undef CP16
#undef CP_COMMIT
}

// ---------------------------------------------------------------------------
extern "C" void kernel_launch(void* const* d_in, const int* in_sizes, int n_in,
                              void* d_out, int out_size)
{
    const float* hidden = (const float*)d_in[0];
    const float* cosb   = (const float*)d_in[1];
    const float* sinb   = (const float*)d_in[2];
    const float* Wq = (const float*)d_in[4];
    const float* Wk = (const float*)d_in[5];
    const float* Wv = (const float*)d_in[6];
    const float* Wo = (const float*)d_in[7];
    const float* qw = (const float*)d_in[8];
    const float* kw = (const float*)d_in[9];
    float* out = (float*)d_out;

    cudaFuncSetAttribute(hgemm_qkv, cudaFuncAttributeMaxDynamicSharedMemorySize, HGEMM_SMEM);
    cudaFuncSetAttribute(hgemm_o,   cudaFuncAttributeMaxDynamicSharedMemorySize, HGEMM_SMEM);
    cudaFuncSetAttribute(flash_attn_tc, cudaFuncAttributeMaxDynamicSharedMemorySize, FLASH_SMEM_TC);

    split_all<<<2048, 256>>>((const float4*)hidden, (const float4*)Wq,
                             (const float4*)Wk, (const float4*)Wv,
                             (const float4*)Wo);

    // QKV projections with fused rmsnorm+rope (Q,K) and transpose (V)
    hgemm_qkv<<<768, 256, HGEMM_SMEM>>>(cosb, sinb, qw, kw);

    flash_attn_tc<<<dim3(16, 32), 256, FLASH_SMEM_TC>>>();

    hgemm_o<<<dim3(32, 16), 256, HGEMM_SMEM>>>(out);
}

// round 15
// speedup vs baseline: 1.0778x; 1.0778x over previous
#include <cuda_runtime.h>
#include <cuda_fp16.h>
#include <math.h>
#include <stdint.h>

#define S_LEN   2048
#define D_MODEL 4096
#define NQH     32
#define NKVH    8
#define HD      128
#define KV_DIM  1024
#define SCALE_F 0.08838834764831845f   // 128^-0.5

// fp32 QKV projection outputs
__device__ float g_q[S_LEN * D_MODEL];
__device__ float g_k[S_LEN * KV_DIM];
__device__ float g_v[S_LEN * KV_DIM];
// fp16 planes
__device__ __half g_hh[S_LEN * D_MODEL];
__device__ __half g_wqh[D_MODEL * D_MODEL];
__device__ __half g_wkh[KV_DIM * D_MODEL];
__device__ __half g_wvh[KV_DIM * D_MODEL];
__device__ __half g_woh[D_MODEL * D_MODEL];
__device__ __half g_ah[S_LEN * D_MODEL];
// fp16 flash inputs
__device__ __half g_qh[S_LEN * D_MODEL];
__device__ __half g_kh[S_LEN * KV_DIM];
__device__ __half g_vt[KV_DIM * S_LEN];

// ---------------------------------------------------------------------------
// helpers
// ---------------------------------------------------------------------------
__device__ __forceinline__ void mma_f16(float (&d)[4],
    uint32_t a0, uint32_t a1, uint32_t a2, uint32_t a3,
    uint32_t b0, uint32_t b1) {
    asm volatile(
        "mma.sync.aligned.m16n8k16.row.col.f32.f16.f16.f32 "
        "{%0,%1,%2,%3}, {%4,%5,%6,%7}, {%8,%9}, {%0,%1,%2,%3};\n"
        : "+f"(d[0]), "+f"(d[1]), "+f"(d[2]), "+f"(d[3])
        : "r"(a0), "r"(a1), "r"(a2), "r"(a3), "r"(b0), "r"(b1));
}

__device__ __forceinline__ void ldsm4(uint32_t (&r)[4], uint32_t addr) {
    asm volatile("ldmatrix.sync.aligned.m8n8.x4.shared.b16 {%0,%1,%2,%3}, [%4];"
        : "=r"(r[0]), "=r"(r[1]), "=r"(r[2]), "=r"(r[3]) : "r"(addr));
}

__device__ __forceinline__ void split2h(float x0, float x1,
                                        __half2& hi, __half2& lo) {
    hi = __floats2half2_rn(x0, x1);
    float2 hf = __half22float2(hi);
    lo = __floats2half2_rn(x0 - hf.x, x1 - hf.y);
}

__device__ __forceinline__ uint32_t h2u(__half2 v) {
    return *reinterpret_cast<uint32_t*>(&v);
}

// ---------------------------------------------------------------------------
// pre-pass: all fp32->fp16 conversions in ONE launch
// ---------------------------------------------------------------------------
#define SEG0 (2 * 1024 * 1024)
#define SEG1 (SEG0 + 4 * 1024 * 1024)
#define SEG2 (SEG1 + 1024 * 1024)
#define SEG3 (SEG2 + 1024 * 1024)
#define SEG4 (SEG3 + 4 * 1024 * 1024)

__global__ __launch_bounds__(256)
void split_all(const float4* __restrict__ hidden, const float4* __restrict__ Wq,
               const float4* __restrict__ Wk, const float4* __restrict__ Wv,
               const float4* __restrict__ Wo)
{
    int stride = gridDim.x * blockDim.x;
    for (int i = blockIdx.x * blockDim.x + threadIdx.x; i < SEG4; i += stride) {
        const float4* src;
        uint2* hi;
        int off;
        if (i < SEG0)      { src = hidden; off = i;        hi = (uint2*)g_hh; }
        else if (i < SEG1) { src = Wq;     off = i - SEG0; hi = (uint2*)g_wqh; }
        else if (i < SEG2) { src = Wk;     off = i - SEG1; hi = (uint2*)g_wkh; }
        else if (i < SEG3) { src = Wv;     off = i - SEG2; hi = (uint2*)g_wvh; }
        else               { src = Wo;     off = i - SEG3; hi = (uint2*)g_woh; }
        float4 v = src[off];
        hi[off] = make_uint2(h2u(__floats2half2_rn(v.x, v.y)),
                             h2u(__floats2half2_rn(v.z, v.w)));
    }
}

// ---------------------------------------------------------------------------
// fp16 1-term GEMM NT with cp.async (R13 verbatim)
// ---------------------------------------------------------------------------
#define LDBH   40
#define AP_H   (128 * LDBH)
#define STG_B  (2 * AP_H * 2)
#define HGEMM_SMEM (4 * STG_B)           // 81920 B

__device__ __forceinline__ void hgemm_body(const __half* __restrict__ Ah,
                                           const __half* __restrict__ Bh,
                                           float* __restrict__ C,
                                           int N, int K, int bx, int by)
{
    extern __shared__ char smc[];
    const uint32_t smem_u32 = (uint32_t)__cvta_generic_to_shared(smc);

    const int tid  = threadIdx.x;
    const int warp = tid >> 5;
    const int lane = tid & 31;
    const int g    = lane >> 2;
    const int t    = lane & 3;
    const int wm   = (warp & 3) * 32;
    const int wn   = (warp >> 2) * 64;

    uint32_t dst_off[4];
    const __half* src[4];
#pragma unroll
    for (int j = 0; j < 4; j++) {
        int cid = tid + j * 256;
        if (cid < 512) {
            int r = cid >> 2, c = cid & 3;
            dst_off[j] = (uint32_t)(r * LDBH + c * 8) * 2;
            src[j] = Ah + (size_t)(by * 128 + r) * K + c * 8;
        } else {
            int b = cid - 512;
            int r = b >> 2, c = b & 3;
            dst_off[j] = (uint32_t)(AP_H + r * LDBH + c * 8) * 2;
            src[j] = Bh + (size_t)(bx * 128 + r) * K + c * 8;
        }
    }

    const int lane8 = lane & 7;
    const uint32_t a_off = (uint32_t)(((wm + lane8 + ((lane >> 3) & 1) * 8) * LDBH
                                      + (lane >> 4) * 8) * 2);
    const uint32_t b_off = (uint32_t)((AP_H + (wn + lane8 + (lane >> 4) * 8) * LDBH
                                      + ((lane >> 3) & 1) * 8) * 2);

    float acc[2][8][4];
#pragma unroll
    for (int mt = 0; mt < 2; mt++)
#pragma unroll
        for (int nt = 0; nt < 8; nt++)
#pragma unroll
            for (int c = 0; c < 4; c++) acc[mt][nt][c] = 0.0f;

    const int nk = K / 32;

#define CP_ISSUE(KT)                                                           \
    {                                                                          \
        uint32_t sb_ = smem_u32 + (uint32_t)(((KT) & 3) * STG_B);              \
        _Pragma("unroll")                                                      \
        for (int j = 0; j < 4; j++) {                                          \
            asm volatile("cp.async.cg.shared.global [%0], [%1], 16;"           \
                :: "r"(sb_ + dst_off[j]), "l"(src[j] + (KT) * 32) : "memory"); \
        }                                                                      \
    }
#define CP_COMMIT() asm volatile("cp.async.commit_group;" ::: "memory")

    CP_ISSUE(0); CP_COMMIT();
    CP_ISSUE(1); CP_COMMIT();
    CP_ISSUE(2); CP_COMMIT();

    for (int kt = 0; kt < nk; kt++) {
        asm volatile("cp.async.wait_group 2;" ::: "memory");
        __syncthreads();
        if (kt + 3 < nk) { CP_ISSUE(kt + 3); }
        CP_COMMIT();

        const uint32_t sb = smem_u32 + (uint32_t)((kt & 3) * STG_B);

#pragma unroll
        for (int k16 = 0; k16 < 2; k16++) {
            uint32_t ah[2][4];
            ldsm4(ah[0], sb + a_off + k16 * 32);
            ldsm4(ah[1], sb + a_off + 16 * LDBH * 2 + k16 * 32);

#pragma unroll
            for (int jh = 0; jh < 2; jh++) {
                uint32_t bh[2][4];
#pragma unroll
                for (int jj = 0; jj < 2; jj++) {
                    int j = jh * 2 + jj;
                    ldsm4(bh[jj], sb + b_off + j * 16 * LDBH * 2 + k16 * 32);
                }
#pragma unroll
                for (int mt = 0; mt < 2; mt++)
#pragma unroll
                    for (int jj = 0; jj < 2; jj++) {
                        int nt = (jh * 2 + jj) * 2;
                        mma_f16(acc[mt][nt], ah[mt][0], ah[mt][1], ah[mt][2],
                                ah[mt][3], bh[jj][0], bh[jj][1]);
                        mma_f16(acc[mt][nt + 1], ah[mt][0], ah[mt][1], ah[mt][2],
                                ah[mt][3], bh[jj][2], bh[jj][3]);
                    }
            }
        }
    }

#pragma unroll
    for (int mt = 0; mt < 2; mt++) {
        int r0 = by * 128 + wm + mt * 16 + g;
#pragma unroll
        for (int nt = 0; nt < 8; nt++) {
            int c0 = bx * 128 + wn + nt * 8 + 2 * t;
            *(float2*)&C[(size_t)r0 * N + c0] =
                make_float2(acc[mt][nt][0], acc[mt][nt][1]);
            *(float2*)&C[(size_t)(r0 + 8) * N + c0] =
                make_float2(acc[mt][nt][2], acc[mt][nt][3]);
        }
    }
#undef CP_ISSUE
#undef CP_COMMIT
}

__global__ __launch_bounds__(256, 2)
void hgemm_qkv()
{
    int b = blockIdx.x;
    if (b < 512)      hgemm_body(g_hh, g_wqh, g_q, 4096, 4096, b & 31, b >> 5);
    else if (b < 640) { int i = b - 512; hgemm_body(g_hh, g_wkh, g_k, 1024, 4096, i & 7, i >> 3); }
    else              { int i = b - 640; hgemm_body(g_hh, g_wvh, g_v, 1024, 4096, i & 7, i >> 3); }
}

__global__ __launch_bounds__(256, 2)
void hgemm_o(float* __restrict__ out)
{
    hgemm_body(g_ah, g_woh, out, 4096, 4096, blockIdx.x, blockIdx.y);
}

// ---------------------------------------------------------------------------
// Fused per-head RMSNorm + RoPE (R13 verbatim)
// ---------------------------------------------------------------------------
__global__ __launch_bounds__(256)
void rmsnorm_rope(const float* __restrict__ cosb, const float* __restrict__ sinb,
                  const float* __restrict__ qw, const float* __restrict__ kw)
{
    const int warp = blockIdx.x * 8 + (threadIdx.x >> 5);
    const int lane = threadIdx.x & 31;

    const float* base;
    const float* w;
    int s;
    bool is_q = warp < S_LEN * NQH;
    size_t off;
    if (is_q) {
        s = warp / NQH;
        int h = warp - s * NQH;
        off = (size_t)s * D_MODEL + h * HD;
        base = g_q + off;
        w = qw;
    } else {
        int wv = warp - S_LEN * NQH;
        s = wv / NKVH;
        int h = wv - s * NKVH;
        off = (size_t)s * KV_DIM + h * HD;
        base = g_k + off;
        w = kw;
    }

    float x0 = base[lane];
    float x1 = base[lane + 32];
    float x2 = base[lane + 64];
    float x3 = base[lane + 96];

    float ss = x0 * x0 + x1 * x1 + x2 * x2 + x3 * x3;
#pragma unroll
    for (int o = 16; o; o >>= 1) ss += __shfl_xor_sync(0xffffffffu, ss, o);
    float inv = rsqrtf(ss * (1.0f / 128.0f) + 1e-6f);

    float n0 = w[lane]      * x0 * inv;
    float n1 = w[lane + 32] * x1 * inv;
    float n2 = w[lane + 64] * x2 * inv;
    float n3 = w[lane + 96] * x3 * inv;

    const float c0 = cosb[s * 64 + lane];
    const float c1 = cosb[s * 64 + lane + 32];
    const float s0 = sinb[s * 64 + lane];
    const float s1 = sinb[s * 64 + lane + 32];

    float r0 = n0 * c0 - n2 * s0;
    float r1 = n1 * c1 - n3 * s1;
    float r2 = n2 * c0 + n0 * s0;
    float r3 = n3 * c1 + n1 * s1;

    __half* dst = is_q ? g_qh : g_kh;
    dst[off + lane]      = __float2half_rn(r0);
    dst[off + lane + 32] = __float2half_rn(r1);
    dst[off + lane + 64] = __float2half_rn(r2);
    dst[off + lane + 96] = __float2half_rn(r3);
}

// ---------------------------------------------------------------------------
// V transpose (R13 verbatim)
// ---------------------------------------------------------------------------
__global__ __launch_bounds__(256)
void vtrans()
{
    __shared__ float tile[32][33];
    const int kvh = blockIdx.z;
    const int s0 = blockIdx.x * 32;
    const int d0 = blockIdx.y * 32;
    const int tx = threadIdx.x;
    const int ty = threadIdx.y;

#pragma unroll
    for (int i = 0; i < 4; i++) {
        int sl = ty + i * 8;
        tile[sl][tx] = g_v[(size_t)(s0 + sl) * KV_DIM + kvh * HD + d0 + tx];
    }
    __syncthreads();
#pragma unroll
    for (int i = 0; i < 4; i++) {
        int dl = ty + i * 8;
        g_vt[(size_t)(kvh * HD + d0 + dl) * S_LEN + s0 + tx] =
            __float2half_rn(tile[tx][dl]);
    }
}

// ---------------------------------------------------------------------------
// Flash attention: Q single fp16, fp16 1-term QK / 2-term PV.
// CHANGE vs R13: 2 KV buffers (smem 106496 B) + __launch_bounds__(256,2)
// -> 2 CTAs/SM (16 warps). Syncs restructured: compute guarded (not
// continue'd) so both __syncthreads are uniform; buffer kt&1 reused only
// after the post-compute barrier.
// ---------------------------------------------------------------------------
#define OFF_QH   0
#define OFF_FKV  17408
#define FKVBUF   17920
#define FLASH_SMEM_TC ((OFF_FKV + 2 * FKVBUF) * 2)   // 106496 B

__global__ __launch_bounds__(256, 2)
void flash_attn_tc()
{
    extern __shared__ __half smh[];

    const int qt  = 15 - blockIdx.x;
    const int h   = blockIdx.y;
    const int q0  = qt * 128;
    const int kvh = h >> 2;
    const int tid  = threadIdx.x;
    const int warp = tid >> 5;
    const int lane = tid & 31;
    const int g = lane >> 2;
    const int t = lane & 3;

    const uint32_t sbase = (uint32_t)__cvta_generic_to_shared(smh);

#define CP16(DST, SRC)                                                         \
    asm volatile("cp.async.cg.shared.global [%0], [%1], 16;"                   \
                 :: "r"(DST), "l"(SRC) : "memory")
#define CP_COMMIT() asm volatile("cp.async.commit_group;" ::: "memory")

#define LOAD_KV(KT, BUF)                                                       \
    {                                                                          \
        const uint32_t kb_ = sbase + (uint32_t)(OFF_FKV + (BUF) * FKVBUF) * 2; \
        const int k0_ = (KT) * 64;                                             \
        _Pragma("unroll")                                                      \
        for (int j = 0; j < 8; j++) {                                          \
            int cid = tid + j * 256;                                           \
            if (cid < 1024) {                                                  \
                int r = cid >> 4, c = cid & 15;                                \
                CP16(kb_ + (uint32_t)(r * 136 + c * 8) * 2,                    \
                     g_kh + (size_t)(k0_ + r) * KV_DIM + kvh * HD + c * 8);    \
            } else {                                                           \
                int b = cid - 1024;                                            \
                int r = b >> 3, c = b & 7;                                     \
                CP16(kb_ + (uint32_t)(8704 + r * 72 + c * 8) * 2,              \
                     g_vt + (size_t)(kvh * HD + r) * S_LEN + k0_ + c * 8);     \
            }                                                                  \
        }                                                                      \
    }

    const int wrow = q0 + warp * 16;
    const int nkt  = 2 * qt + 2;

    // prologue: Q + KV0 in group 0; KV1 in group 1
#pragma unroll
    for (int j = 0; j < 8; j++) {
        int cid = tid + j * 256;
        int r = cid >> 4, c = cid & 15;
        CP16(sbase + (uint32_t)(OFF_QH + r * 136 + c * 8) * 2,
             g_qh + (size_t)(q0 + r) * D_MODEL + h * HD + c * 8);
    }
    LOAD_KV(0, 0);
    CP_COMMIT();
    if (1 < nkt) LOAD_KV(1, 1);
    CP_COMMIT();

    float o[16][4];
#pragma unroll
    for (int nt = 0; nt < 16; nt++)
#pragma unroll
        for (int j = 0; j < 4; j++) o[nt][j] = 0.0f;
    float m0 = -1e30f, m1 = -1e30f, l0 = 0.0f, l1 = 0.0f;

    const __half* qrh = smh + OFF_QH + (warp * 16 + g) * 136 + 2 * t;

    for (int kt = 0; kt < nkt; kt++) {
        const int k0 = kt * 64;
        asm volatile("cp.async.wait_group 1;" ::: "memory");
        __syncthreads();

        if (k0 <= wrow + 15) {
            const __half* Kh = smh + OFF_FKV + (kt & 1) * FKVBUF;
            const __half* Vh = Kh + 8704;

            // ---- S = Q K^T (fp16 single-term) ----
            float s[8][4];
#pragma unroll
            for (int nt = 0; nt < 8; nt++)
#pragma unroll
                for (int j = 0; j < 4; j++) s[nt][j] = 0.0f;

#pragma unroll
            for (int c = 0; c < 8; c++) {
                uint32_t ah0 = *(const uint32_t*)(qrh + c * 16);
                uint32_t ah1 = *(const uint32_t*)(qrh + 8 * 136 + c * 16);
                uint32_t ah2 = *(const uint32_t*)(qrh + c * 16 + 8);
                uint32_t ah3 = *(const uint32_t*)(qrh + 8 * 136 + c * 16 + 8);
#pragma unroll
                for (int nt = 0; nt < 8; nt++) {
                    const __half* kp = Kh + (nt * 8 + g) * 136 + c * 16 + 2 * t;
                    uint32_t b0 = *(const uint32_t*)(kp);
                    uint32_t b1 = *(const uint32_t*)(kp + 8);
                    mma_f16(s[nt], ah0, ah1, ah2, ah3, b0, b1);
                }
            }

            // ---- scale + causal mask ----
            if (k0 + 63 > wrow) {
                int r0 = wrow + g, r1 = r0 + 8;
#pragma unroll
                for (int nt = 0; nt < 8; nt++) {
                    int c0 = k0 + nt * 8 + 2 * t;
                    s[nt][0] = (c0     > r0) ? -1e30f : s[nt][0] * SCALE_F;
                    s[nt][1] = (c0 + 1 > r0) ? -1e30f : s[nt][1] * SCALE_F;
                    s[nt][2] = (c0     > r1) ? -1e30f : s[nt][2] * SCALE_F;
                    s[nt][3] = (c0 + 1 > r1) ? -1e30f : s[nt][3] * SCALE_F;
                }
            } else {
#pragma unroll
                for (int nt = 0; nt < 8; nt++)
#pragma unroll
                    for (int j = 0; j < 4; j++) s[nt][j] *= SCALE_F;
            }

            // ---- online softmax ----
            float mx0 = -1e30f, mx1 = -1e30f;
#pragma unroll
            for (int nt = 0; nt < 8; nt++) {
                mx0 = fmaxf(mx0, fmaxf(s[nt][0], s[nt][1]));
                mx1 = fmaxf(mx1, fmaxf(s[nt][2], s[nt][3]));
            }
            mx0 = fmaxf(mx0, __shfl_xor_sync(0xffffffffu, mx0, 1));
            mx0 = fmaxf(mx0, __shfl_xor_sync(0xffffffffu, mx0, 2));
            mx1 = fmaxf(mx1, __shfl_xor_sync(0xffffffffu, mx1, 1));
            mx1 = fmaxf(mx1, __shfl_xor_sync(0xffffffffu, mx1, 2));

            float mn0 = fmaxf(m0, mx0), mn1 = fmaxf(m1, mx1);
            float a0 = __expf(m0 - mn0), a1 = __expf(m1 - mn1);
            m0 = mn0; m1 = mn1;

            float sum0 = 0.0f, sum1 = 0.0f;
#pragma unroll
            for (int nt = 0; nt < 8; nt++) {
                s[nt][0] = __expf(s[nt][0] - m0);
                s[nt][1] = __expf(s[nt][1] - m0);
                s[nt][2] = __expf(s[nt][2] - m1);
                s[nt][3] = __expf(s[nt][3] - m1);
                sum0 += s[nt][0] + s[nt][1];
                sum1 += s[nt][2] + s[nt][3];
            }
            sum0 += __shfl_xor_sync(0xffffffffu, sum0, 1);
            sum0 += __shfl_xor_sync(0xffffffffu, sum0, 2);
            sum1 += __shfl_xor_sync(0xffffffffu, sum1, 1);
            sum1 += __shfl_xor_sync(0xffffffffu, sum1, 2);
            l0 = l0 * a0 + sum0;
            l1 = l1 * a1 + sum1;

#pragma unroll
            for (int nt = 0; nt < 16; nt++) {
                o[nt][0] *= a0; o[nt][1] *= a0;
                o[nt][2] *= a1; o[nt][3] *= a1;
            }

            // ---- O += P V (fp16: P 2-term split, V single) ----
#pragma unroll
            for (int c = 0; c < 4; c++) {
                __half2 h0, lo0, h1, lo1, h2, lo2, h3, lo3;
                split2h(s[2 * c][0],     s[2 * c][1],     h0, lo0);
                split2h(s[2 * c][2],     s[2 * c][3],     h1, lo1);
                split2h(s[2 * c + 1][0], s[2 * c + 1][1], h2, lo2);
                split2h(s[2 * c + 1][2], s[2 * c + 1][3], h3, lo3);
                uint32_t ph0 = h2u(h0), ph1 = h2u(h1), ph2 = h2u(h2), ph3 = h2u(h3);
                uint32_t pl0 = h2u(lo0), pl1 = h2u(lo1), pl2 = h2u(lo2), pl3 = h2u(lo3);
#pragma unroll
                for (int nt = 0; nt < 16; nt++) {
                    const __half* vp = Vh + (nt * 8 + g) * 72 + c * 16 + 2 * t;
                    uint32_t vh0 = *(const uint32_t*)(vp);
                    uint32_t vh1 = *(const uint32_t*)(vp + 8);
                    mma_f16(o[nt], ph0, ph1, ph2, ph3, vh0, vh1);
                    mma_f16(o[nt], pl0, pl1, pl2, pl3, vh0, vh1);
                }
            }
        }

        __syncthreads();                 // all warps done reading buf kt&1
        if (kt + 2 < nkt) LOAD_KV(kt + 2, kt & 1);
        CP_COMMIT();
    }

    // ---- normalize + write attn output as single fp16 plane ----
    float inv0 = 1.0f / l0, inv1 = 1.0f / l1;
    int row0 = q0 + warp * 16 + g;
#pragma unroll
    for (int nt = 0; nt < 16; nt++) {
        int col = h * HD + nt * 8 + 2 * t;
        *(uint32_t*)&g_ah[(size_t)row0 * D_MODEL + col] =
            h2u(__floats2half2_rn(o[nt][0] * inv0, o[nt][1] * inv0));
        *(uint32_t*)&g_ah[(size_t)(row0 + 8) * D_MODEL + col] =
            h2u(__floats2half2_rn(o[nt][2] * inv1, o[nt][3] * inv1));
    }
#undef LOAD_KV
#undef CP16
#undef CP_COMMIT
}

// ---------------------------------------------------------------------------
extern "C" void kernel_launch(void* const* d_in, const int* in_sizes, int n_in,
                              void* d_out, int out_size)
{
    const float* hidden = (const float*)d_in[0];
    const float* cosb   = (const float*)d_in[1];
    const float* sinb   = (const float*)d_in[2];
    const float* Wq = (const float*)d_in[4];
    const float* Wk = (const float*)d_in[5];
    const float* Wv = (const float*)d_in[6];
    const float* Wo = (const float*)d_in[7];
    const float* qw = (const float*)d_in[8];
    const float* kw = (const float*)d_in[9];
    float* out = (float*)d_out;

    cudaFuncSetAttribute(hgemm_qkv, cudaFuncAttributeMaxDynamicSharedMemorySize, HGEMM_SMEM);
    cudaFuncSetAttribute(hgemm_o,   cudaFuncAttributeMaxDynamicSharedMemorySize, HGEMM_SMEM);
    cudaFuncSetAttribute(flash_attn_tc, cudaFuncAttributeMaxDynamicSharedMemorySize, FLASH_SMEM_TC);

    split_all<<<2048, 256>>>((const float4*)hidden, (const float4*)Wq,
                             (const float4*)Wk, (const float4*)Wv,
                             (const float4*)Wo);

    hgemm_qkv<<<768, 256, HGEMM_SMEM>>>();

    rmsnorm_rope<<<10240, 256>>>(cosb, sinb, qw, kw);
    vtrans<<<dim3(64, 4, 8), dim3(32, 8)>>>();

    flash_attn_tc<<<dim3(16, 32), 256, FLASH_SMEM_TC>>>();

    hgemm_o<<<dim3(32, 16), 256, HGEMM_SMEM>>>(out);
}

// round 16
// speedup vs baseline: 1.1226x; 1.0415x over previous
#include <cuda_runtime.h>
#include <cuda_fp16.h>
#include <math.h>
#include <stdint.h>

#define S_LEN   2048
#define D_MODEL 4096
#define NQH     32
#define NKVH    8
#define HD      128
#define KV_DIM  1024
#define SCALE_F 0.08838834764831845f   // 128^-0.5

// fp32 QKV projection outputs
__device__ float g_q[S_LEN * D_MODEL];
__device__ float g_k[S_LEN * KV_DIM];
__device__ float g_v[S_LEN * KV_DIM];
// fp16 planes
__device__ __half g_hh[S_LEN * D_MODEL];
__device__ __half g_wqh[D_MODEL * D_MODEL];
__device__ __half g_wkh[KV_DIM * D_MODEL];
__device__ __half g_wvh[KV_DIM * D_MODEL];
__device__ __half g_woh[D_MODEL * D_MODEL];
__device__ __half g_ah[S_LEN * D_MODEL];
// fp16 flash inputs
__device__ __half g_qh[S_LEN * D_MODEL];
__device__ __half g_kh[S_LEN * KV_DIM];
__device__ __half g_vt[KV_DIM * S_LEN];

// ---------------------------------------------------------------------------
// helpers
// ---------------------------------------------------------------------------
__device__ __forceinline__ void mma_f16(float (&d)[4],
    uint32_t a0, uint32_t a1, uint32_t a2, uint32_t a3,
    uint32_t b0, uint32_t b1) {
    asm volatile(
        "mma.sync.aligned.m16n8k16.row.col.f32.f16.f16.f32 "
        "{%0,%1,%2,%3}, {%4,%5,%6,%7}, {%8,%9}, {%0,%1,%2,%3};\n"
        : "+f"(d[0]), "+f"(d[1]), "+f"(d[2]), "+f"(d[3])
        : "r"(a0), "r"(a1), "r"(a2), "r"(a3), "r"(b0), "r"(b1));
}

__device__ __forceinline__ void ldsm4(uint32_t (&r)[4], uint32_t addr) {
    asm volatile("ldmatrix.sync.aligned.m8n8.x4.shared.b16 {%0,%1,%2,%3}, [%4];"
        : "=r"(r[0]), "=r"(r[1]), "=r"(r[2]), "=r"(r[3]) : "r"(addr));
}

__device__ __forceinline__ void split2h(float x0, float x1,
                                        __half2& hi, __half2& lo) {
    hi = __floats2half2_rn(x0, x1);
    float2 hf = __half22float2(hi);
    lo = __floats2half2_rn(x0 - hf.x, x1 - hf.y);
}

__device__ __forceinline__ uint32_t h2u(__half2 v) {
    return *reinterpret_cast<uint32_t*>(&v);
}

// ---------------------------------------------------------------------------
// pre-pass: all fp32->fp16 conversions in ONE launch
// ---------------------------------------------------------------------------
#define SEG0 (2 * 1024 * 1024)
#define SEG1 (SEG0 + 4 * 1024 * 1024)
#define SEG2 (SEG1 + 1024 * 1024)
#define SEG3 (SEG2 + 1024 * 1024)
#define SEG4 (SEG3 + 4 * 1024 * 1024)

__global__ __launch_bounds__(256)
void split_all(const float4* __restrict__ hidden, const float4* __restrict__ Wq,
               const float4* __restrict__ Wk, const float4* __restrict__ Wv,
               const float4* __restrict__ Wo)
{
    int stride = gridDim.x * blockDim.x;
    for (int i = blockIdx.x * blockDim.x + threadIdx.x; i < SEG4; i += stride) {
        const float4* src;
        uint2* hi;
        int off;
        if (i < SEG0)      { src = hidden; off = i;        hi = (uint2*)g_hh; }
        else if (i < SEG1) { src = Wq;     off = i - SEG0; hi = (uint2*)g_wqh; }
        else if (i < SEG2) { src = Wk;     off = i - SEG1; hi = (uint2*)g_wkh; }
        else if (i < SEG3) { src = Wv;     off = i - SEG2; hi = (uint2*)g_wvh; }
        else               { src = Wo;     off = i - SEG3; hi = (uint2*)g_woh; }
        float4 v = src[off];
        hi[off] = make_uint2(h2u(__floats2half2_rn(v.x, v.y)),
                             h2u(__floats2half2_rn(v.z, v.w)));
    }
}

// ---------------------------------------------------------------------------
// fp16 1-term GEMM NT with cp.async (R13 verbatim)
// ---------------------------------------------------------------------------
#define LDBH   40
#define AP_H   (128 * LDBH)
#define STG_B  (2 * AP_H * 2)
#define HGEMM_SMEM (4 * STG_B)           // 81920 B

__device__ __forceinline__ void hgemm_body(const __half* __restrict__ Ah,
                                           const __half* __restrict__ Bh,
                                           float* __restrict__ C,
                                           int N, int K, int bx, int by)
{
    extern __shared__ char smc[];
    const uint32_t smem_u32 = (uint32_t)__cvta_generic_to_shared(smc);

    const int tid  = threadIdx.x;
    const int warp = tid >> 5;
    const int lane = tid & 31;
    const int g    = lane >> 2;
    const int t    = lane & 3;
    const int wm   = (warp & 3) * 32;
    const int wn   = (warp >> 2) * 64;

    uint32_t dst_off[4];
    const __half* src[4];
#pragma unroll
    for (int j = 0; j < 4; j++) {
        int cid = tid + j * 256;
        if (cid < 512) {
            int r = cid >> 2, c = cid & 3;
            dst_off[j] = (uint32_t)(r * LDBH + c * 8) * 2;
            src[j] = Ah + (size_t)(by * 128 + r) * K + c * 8;
        } else {
            int b = cid - 512;
            int r = b >> 2, c = b & 3;
            dst_off[j] = (uint32_t)(AP_H + r * LDBH + c * 8) * 2;
            src[j] = Bh + (size_t)(bx * 128 + r) * K + c * 8;
        }
    }

    const int lane8 = lane & 7;
    const uint32_t a_off = (uint32_t)(((wm + lane8 + ((lane >> 3) & 1) * 8) * LDBH
                                      + (lane >> 4) * 8) * 2);
    const uint32_t b_off = (uint32_t)((AP_H + (wn + lane8 + (lane >> 4) * 8) * LDBH
                                      + ((lane >> 3) & 1) * 8) * 2);

    float acc[2][8][4];
#pragma unroll
    for (int mt = 0; mt < 2; mt++)
#pragma unroll
        for (int nt = 0; nt < 8; nt++)
#pragma unroll
            for (int c = 0; c < 4; c++) acc[mt][nt][c] = 0.0f;

    const int nk = K / 32;

#define CP_ISSUE(KT)                                                           \
    {                                                                          \
        uint32_t sb_ = smem_u32 + (uint32_t)(((KT) & 3) * STG_B);              \
        _Pragma("unroll")                                                      \
        for (int j = 0; j < 4; j++) {                                          \
            asm volatile("cp.async.cg.shared.global [%0], [%1], 16;"           \
                :: "r"(sb_ + dst_off[j]), "l"(src[j] + (KT) * 32) : "memory"); \
        }                                                                      \
    }
#define CP_COMMIT() asm volatile("cp.async.commit_group;" ::: "memory")

    CP_ISSUE(0); CP_COMMIT();
    CP_ISSUE(1); CP_COMMIT();
    CP_ISSUE(2); CP_COMMIT();

    for (int kt = 0; kt < nk; kt++) {
        asm volatile("cp.async.wait_group 2;" ::: "memory");
        __syncthreads();
        if (kt + 3 < nk) { CP_ISSUE(kt + 3); }
        CP_COMMIT();

        const uint32_t sb = smem_u32 + (uint32_t)((kt & 3) * STG_B);

#pragma unroll
        for (int k16 = 0; k16 < 2; k16++) {
            uint32_t ah[2][4];
            ldsm4(ah[0], sb + a_off + k16 * 32);
            ldsm4(ah[1], sb + a_off + 16 * LDBH * 2 + k16 * 32);

#pragma unroll
            for (int jh = 0; jh < 2; jh++) {
                uint32_t bh[2][4];
#pragma unroll
                for (int jj = 0; jj < 2; jj++) {
                    int j = jh * 2 + jj;
                    ldsm4(bh[jj], sb + b_off + j * 16 * LDBH * 2 + k16 * 32);
                }
#pragma unroll
                for (int mt = 0; mt < 2; mt++)
#pragma unroll
                    for (int jj = 0; jj < 2; jj++) {
                        int nt = (jh * 2 + jj) * 2;
                        mma_f16(acc[mt][nt], ah[mt][0], ah[mt][1], ah[mt][2],
                                ah[mt][3], bh[jj][0], bh[jj][1]);
                        mma_f16(acc[mt][nt + 1], ah[mt][0], ah[mt][1], ah[mt][2],
                                ah[mt][3], bh[jj][2], bh[jj][3]);
                    }
            }
        }
    }

#pragma unroll
    for (int mt = 0; mt < 2; mt++) {
        int r0 = by * 128 + wm + mt * 16 + g;
#pragma unroll
        for (int nt = 0; nt < 8; nt++) {
            int c0 = bx * 128 + wn + nt * 8 + 2 * t;
            *(float2*)&C[(size_t)r0 * N + c0] =
                make_float2(acc[mt][nt][0], acc[mt][nt][1]);
            *(float2*)&C[(size_t)(r0 + 8) * N + c0] =
                make_float2(acc[mt][nt][2], acc[mt][nt][3]);
        }
    }
#undef CP_ISSUE
#undef CP_COMMIT
}

__global__ __launch_bounds__(256, 2)
void hgemm_qkv()
{
    int b = blockIdx.x;
    if (b < 512)      hgemm_body(g_hh, g_wqh, g_q, 4096, 4096, b & 31, b >> 5);
    else if (b < 640) { int i = b - 512; hgemm_body(g_hh, g_wkh, g_k, 1024, 4096, i & 7, i >> 3); }
    else              { int i = b - 640; hgemm_body(g_hh, g_wvh, g_v, 1024, 4096, i & 7, i >> 3); }
}

__global__ __launch_bounds__(256, 2)
void hgemm_o(float* __restrict__ out)
{
    hgemm_body(g_ah, g_woh, out, 4096, 4096, blockIdx.x, blockIdx.y);
}

// ---------------------------------------------------------------------------
// Fused aux kernel: blocks [0,10240) = per-head RMSNorm+RoPE (R13 logic);
// blocks [10240,12288) = V transpose (R13 logic). Paths touch disjoint data.
// ---------------------------------------------------------------------------
#define NORM_BLOCKS 10240
#define AUX_BLOCKS  (NORM_BLOCKS + 2048)

__global__ __launch_bounds__(256)
void norm_rope_vtrans(const float* __restrict__ cosb,
                      const float* __restrict__ sinb,
                      const float* __restrict__ qw, const float* __restrict__ kw)
{
    if (blockIdx.x < NORM_BLOCKS) {
        const int warp = blockIdx.x * 8 + (threadIdx.x >> 5);
        const int lane = threadIdx.x & 31;

        const float* base;
        const float* w;
        int s;
        bool is_q = warp < S_LEN * NQH;
        size_t off;
        if (is_q) {
            s = warp / NQH;
            int h = warp - s * NQH;
            off = (size_t)s * D_MODEL + h * HD;
            base = g_q + off;
            w = qw;
        } else {
            int wv = warp - S_LEN * NQH;
            s = wv / NKVH;
            int h = wv - s * NKVH;
            off = (size_t)s * KV_DIM + h * HD;
            base = g_k + off;
            w = kw;
        }

        float x0 = base[lane];
        float x1 = base[lane + 32];
        float x2 = base[lane + 64];
        float x3 = base[lane + 96];

        float ss = x0 * x0 + x1 * x1 + x2 * x2 + x3 * x3;
#pragma unroll
        for (int o = 16; o; o >>= 1) ss += __shfl_xor_sync(0xffffffffu, ss, o);
        float inv = rsqrtf(ss * (1.0f / 128.0f) + 1e-6f);

        float n0 = w[lane]      * x0 * inv;
        float n1 = w[lane + 32] * x1 * inv;
        float n2 = w[lane + 64] * x2 * inv;
        float n3 = w[lane + 96] * x3 * inv;

        const float c0 = cosb[s * 64 + lane];
        const float c1 = cosb[s * 64 + lane + 32];
        const float s0 = sinb[s * 64 + lane];
        const float s1 = sinb[s * 64 + lane + 32];

        float r0 = n0 * c0 - n2 * s0;
        float r1 = n1 * c1 - n3 * s1;
        float r2 = n2 * c0 + n0 * s0;
        float r3 = n3 * c1 + n1 * s1;

        __half* dst = is_q ? g_qh : g_kh;
        dst[off + lane]      = __float2half_rn(r0);
        dst[off + lane + 32] = __float2half_rn(r1);
        dst[off + lane + 64] = __float2half_rn(r2);
        dst[off + lane + 96] = __float2half_rn(r3);
    } else {
        // V transpose: block index -> (s-tile 64, d-tile 4, kvh 8)
        __shared__ float tile[32][33];
        int b = blockIdx.x - NORM_BLOCKS;           // 0..2047
        const int kvh = b & 7;
        const int d0  = ((b >> 3) & 3) * 32;
        const int s0  = (b >> 5) * 32;
        const int tx = threadIdx.x & 31;
        const int ty = threadIdx.x >> 5;            // 0..7

#pragma unroll
        for (int i = 0; i < 4; i++) {
            int sl = ty + i * 8;
            tile[sl][tx] = g_v[(size_t)(s0 + sl) * KV_DIM + kvh * HD + d0 + tx];
        }
        __syncthreads();
#pragma unroll
        for (int i = 0; i < 4; i++) {
            int dl = ty + i * 8;
            g_vt[(size_t)(kvh * HD + d0 + dl) * S_LEN + s0 + tx] =
                __float2half_rn(tile[tx][dl]);
        }
    }
}

// ---------------------------------------------------------------------------
// Tensor-core flash attention (R13 verbatim): Q single fp16, 4-stage cp.async
// KV pipeline. QK^T fp16 1-term; P.V fp16 2-term; fp16 epilogue.
// ---------------------------------------------------------------------------
#define OFF_QH   0
#define OFF_FKV  17408
#define FKVBUF   17920
#define FLASH_SMEM_TC ((OFF_FKV + 4 * FKVBUF) * 2)   // 178176 B

__global__ __launch_bounds__(256, 1)
void flash_attn_tc()
{
    extern __shared__ __half smh[];

    const int qt  = 15 - blockIdx.x;
    const int h   = blockIdx.y;
    const int q0  = qt * 128;
    const int kvh = h >> 2;
    const int tid  = threadIdx.x;
    const int warp = tid >> 5;
    const int lane = tid & 31;
    const int g = lane >> 2;
    const int t = lane & 3;

    const uint32_t sbase = (uint32_t)__cvta_generic_to_shared(smh);

#define CP16(DST, SRC)                                                         \
    asm volatile("cp.async.cg.shared.global [%0], [%1], 16;"                   \
                 :: "r"(DST), "l"(SRC) : "memory")
#define CP_COMMIT() asm volatile("cp.async.commit_group;" ::: "memory")

#define LOAD_KV(KT, BUF)                                                       \
    {                                                                          \
        const uint32_t kb_ = sbase + (uint32_t)(OFF_FKV + (BUF) * FKVBUF) * 2; \
        const int k0_ = (KT) * 64;                                             \
        _Pragma("unroll")                                                      \
        for (int j = 0; j < 8; j++) {                                          \
            int cid = tid + j * 256;                                           \
            if (cid < 1024) {                                                  \
                int r = cid >> 4, c = cid & 15;                                \
                CP16(kb_ + (uint32_t)(r * 136 + c * 8) * 2,                    \
                     g_kh + (size_t)(k0_ + r) * KV_DIM + kvh * HD + c * 8);    \
            } else {                                                           \
                int b = cid - 1024;                                            \
                int r = b >> 3, c = b & 7;                                     \
                CP16(kb_ + (uint32_t)(8704 + r * 72 + c * 8) * 2,              \
                     g_vt + (size_t)(kvh * HD + r) * S_LEN + k0_ + c * 8);     \
            }                                                                  \
        }                                                                      \
    }

    const int wrow = q0 + warp * 16;
    const int nkt  = 2 * qt + 2;

#pragma unroll
    for (int j = 0; j < 8; j++) {
        int cid = tid + j * 256;
        int r = cid >> 4, c = cid & 15;
        CP16(sbase + (uint32_t)(OFF_QH + r * 136 + c * 8) * 2,
             g_qh + (size_t)(q0 + r) * D_MODEL + h * HD + c * 8);
    }
    LOAD_KV(0, 0);
    CP_COMMIT();
    if (1 < nkt) LOAD_KV(1, 1);
    CP_COMMIT();
    if (2 < nkt) LOAD_KV(2, 2);
    CP_COMMIT();

    float o[16][4];
#pragma unroll
    for (int nt = 0; nt < 16; nt++)
#pragma unroll
        for (int j = 0; j < 4; j++) o[nt][j] = 0.0f;
    float m0 = -1e30f, m1 = -1e30f, l0 = 0.0f, l1 = 0.0f;

    const __half* qrh = smh + OFF_QH + (warp * 16 + g) * 136 + 2 * t;

    for (int kt = 0; kt < nkt; kt++) {
        const int k0 = kt * 64;
        asm volatile("cp.async.wait_group 2;" ::: "memory");
        __syncthreads();
        if (kt + 3 < nkt) LOAD_KV(kt + 3, (kt + 3) & 3);
        CP_COMMIT();

        if (k0 > wrow + 15) continue;

        const __half* Kh = smh + OFF_FKV + (kt & 3) * FKVBUF;
        const __half* Vh = Kh + 8704;

        float s[8][4];
#pragma unroll
        for (int nt = 0; nt < 8; nt++)
#pragma unroll
            for (int j = 0; j < 4; j++) s[nt][j] = 0.0f;

#pragma unroll
        for (int c = 0; c < 8; c++) {
            uint32_t ah0 = *(const uint32_t*)(qrh + c * 16);
            uint32_t ah1 = *(const uint32_t*)(qrh + 8 * 136 + c * 16);
            uint32_t ah2 = *(const uint32_t*)(qrh + c * 16 + 8);
            uint32_t ah3 = *(const uint32_t*)(qrh + 8 * 136 + c * 16 + 8);
#pragma unroll
            for (int nt = 0; nt < 8; nt++) {
                const __half* kp = Kh + (nt * 8 + g) * 136 + c * 16 + 2 * t;
                uint32_t b0 = *(const uint32_t*)(kp);
                uint32_t b1 = *(const uint32_t*)(kp + 8);
                mma_f16(s[nt], ah0, ah1, ah2, ah3, b0, b1);
            }
        }

        if (k0 + 63 > wrow) {
            int r0 = wrow + g, r1 = r0 + 8;
#pragma unroll
            for (int nt = 0; nt < 8; nt++) {
                int c0 = k0 + nt * 8 + 2 * t;
                s[nt][0] = (c0     > r0) ? -1e30f : s[nt][0] * SCALE_F;
                s[nt][1] = (c0 + 1 > r0) ? -1e30f : s[nt][1] * SCALE_F;
                s[nt][2] = (c0     > r1) ? -1e30f : s[nt][2] * SCALE_F;
                s[nt][3] = (c0 + 1 > r1) ? -1e30f : s[nt][3] * SCALE_F;
            }
        } else {
#pragma unroll
            for (int nt = 0; nt < 8; nt++)
#pragma unroll
                for (int j = 0; j < 4; j++) s[nt][j] *= SCALE_F;
        }

        float mx0 = -1e30f, mx1 = -1e30f;
#pragma unroll
        for (int nt = 0; nt < 8; nt++) {
            mx0 = fmaxf(mx0, fmaxf(s[nt][0], s[nt][1]));
            mx1 = fmaxf(mx1, fmaxf(s[nt][2], s[nt][3]));
        }
        mx0 = fmaxf(mx0, __shfl_xor_sync(0xffffffffu, mx0, 1));
        mx0 = fmaxf(mx0, __shfl_xor_sync(0xffffffffu, mx0, 2));
        mx1 = fmaxf(mx1, __shfl_xor_sync(0xffffffffu, mx1, 1));
        mx1 = fmaxf(mx1, __shfl_xor_sync(0xffffffffu, mx1, 2));

        float mn0 = fmaxf(m0, mx0), mn1 = fmaxf(m1, mx1);
        float a0 = __expf(m0 - mn0), a1 = __expf(m1 - mn1);
        m0 = mn0; m1 = mn1;

        float sum0 = 0.0f, sum1 = 0.0f;
#pragma unroll
        for (int nt = 0; nt < 8; nt++) {
            s[nt][0] = __expf(s[nt][0] - m0);
            s[nt][1] = __expf(s[nt][1] - m0);
            s[nt][2] = __expf(s[nt][2] - m1);
            s[nt][3] = __expf(s[nt][3] - m1);
            sum0 += s[nt][0] + s[nt][1];
            sum1 += s[nt][2] + s[nt][3];
        }
        sum0 += __shfl_xor_sync(0xffffffffu, sum0, 1);
        sum0 += __shfl_xor_sync(0xffffffffu, sum0, 2);
        sum1 += __shfl_xor_sync(0xffffffffu, sum1, 1);
        sum1 += __shfl_xor_sync(0xffffffffu, sum1, 2);
        l0 = l0 * a0 + sum0;
        l1 = l1 * a1 + sum1;

#pragma unroll
        for (int nt = 0; nt < 16; nt++) {
            o[nt][0] *= a0; o[nt][1] *= a0;
            o[nt][2] *= a1; o[nt][3] *= a1;
        }

#pragma unroll
        for (int c = 0; c < 4; c++) {
            __half2 h0, lo0, h1, lo1, h2, lo2, h3, lo3;
            split2h(s[2 * c][0],     s[2 * c][1],     h0, lo0);
            split2h(s[2 * c][2],     s[2 * c][3],     h1, lo1);
            split2h(s[2 * c + 1][0], s[2 * c + 1][1], h2, lo2);
            split2h(s[2 * c + 1][2], s[2 * c + 1][3], h3, lo3);
            uint32_t ph0 = h2u(h0), ph1 = h2u(h1), ph2 = h2u(h2), ph3 = h2u(h3);
            uint32_t pl0 = h2u(lo0), pl1 = h2u(lo1), pl2 = h2u(lo2), pl3 = h2u(lo3);
#pragma unroll
            for (int nt = 0; nt < 16; nt++) {
                const __half* vp = Vh + (nt * 8 + g) * 72 + c * 16 + 2 * t;
                uint32_t vh0 = *(const uint32_t*)(vp);
                uint32_t vh1 = *(const uint32_t*)(vp + 8);
                mma_f16(o[nt], ph0, ph1, ph2, ph3, vh0, vh1);
                mma_f16(o[nt], pl0, pl1, pl2, pl3, vh0, vh1);
            }
        }
    }

    float inv0 = 1.0f / l0, inv1 = 1.0f / l1;
    int row0 = q0 + warp * 16 + g;
#pragma unroll
    for (int nt = 0; nt < 16; nt++) {
        int col = h * HD + nt * 8 + 2 * t;
        *(uint32_t*)&g_ah[(size_t)row0 * D_MODEL + col] =
            h2u(__floats2half2_rn(o[nt][0] * inv0, o[nt][1] * inv0));
        *(uint32_t*)&g_ah[(size_t)(row0 + 8) * D_MODEL + col] =
            h2u(__floats2half2_rn(o[nt][2] * inv1, o[nt][3] * inv1));
    }
#undef LOAD_KV
#undef CP16
#undef CP_COMMIT
}

// ---------------------------------------------------------------------------
extern "C" void kernel_launch(void* const* d_in, const int* in_sizes, int n_in,
                              void* d_out, int out_size)
{
    const float* hidden = (const float*)d_in[0];
    const float* cosb   = (const float*)d_in[1];
    const float* sinb   = (const float*)d_in[2];
    const float* Wq = (const float*)d_in[4];
    const float* Wk = (const float*)d_in[5];
    const float* Wv = (const float*)d_in[6];
    const float* Wo = (const float*)d_in[7];
    const float* qw = (const float*)d_in[8];
    const float* kw = (const float*)d_in[9];
    float* out = (float*)d_out;

    cudaFuncSetAttribute(hgemm_qkv, cudaFuncAttributeMaxDynamicSharedMemorySize, HGEMM_SMEM);
    cudaFuncSetAttribute(hgemm_o,   cudaFuncAttributeMaxDynamicSharedMemorySize, HGEMM_SMEM);
    cudaFuncSetAttribute(flash_attn_tc, cudaFuncAttributeMaxDynamicSharedMemorySize, FLASH_SMEM_TC);

    split_all<<<2048, 256>>>((const float4*)hidden, (const float4*)Wq,
                             (const float4*)Wk, (const float4*)Wv,
                             (const float4*)Wo);

    hgemm_qkv<<<768, 256, HGEMM_SMEM>>>();

    norm_rope_vtrans<<<AUX_BLOCKS, 256>>>(cosb, sinb, qw, kw);

    flash_attn_tc<<<dim3(16, 32), 256, FLASH_SMEM_TC>>>();

    hgemm_o<<<dim3(32, 16), 256, HGEMM_SMEM>>>(out);
}

// round 17
// speedup vs baseline: 1.1279x; 1.0048x over previous
#include <cuda_runtime.h>
#include <cuda_fp16.h>
#include <math.h>
#include <stdint.h>

#define S_LEN   2048
#define D_MODEL 4096
#define NQH     32
#define NKVH    8
#define HD      128
#define KV_DIM  1024
#define SCALE_F 0.08838834764831845f   // 128^-0.5

// fp32 QKV projection outputs
__device__ float g_q[S_LEN * D_MODEL];
__device__ float g_k[S_LEN * KV_DIM];
__device__ float g_v[S_LEN * KV_DIM];
// fp16 planes
__device__ __half g_hh[S_LEN * D_MODEL];
__device__ __half g_wqh[D_MODEL * D_MODEL];
__device__ __half g_wkh[KV_DIM * D_MODEL];
__device__ __half g_wvh[KV_DIM * D_MODEL];
__device__ __half g_woh[D_MODEL * D_MODEL];
__device__ __half g_ah[S_LEN * D_MODEL];
// fp16 flash inputs
__device__ __half g_qh[S_LEN * D_MODEL];
__device__ __half g_kh[S_LEN * KV_DIM];
__device__ __half g_vt[KV_DIM * S_LEN];

// ---------------------------------------------------------------------------
// helpers
// ---------------------------------------------------------------------------
__device__ __forceinline__ void mma_f16(float (&d)[4],
    uint32_t a0, uint32_t a1, uint32_t a2, uint32_t a3,
    uint32_t b0, uint32_t b1) {
    asm volatile(
        "mma.sync.aligned.m16n8k16.row.col.f32.f16.f16.f32 "
        "{%0,%1,%2,%3}, {%4,%5,%6,%7}, {%8,%9}, {%0,%1,%2,%3};\n"
        : "+f"(d[0]), "+f"(d[1]), "+f"(d[2]), "+f"(d[3])
        : "r"(a0), "r"(a1), "r"(a2), "r"(a3), "r"(b0), "r"(b1));
}

__device__ __forceinline__ void ldsm4(uint32_t (&r)[4], uint32_t addr) {
    asm volatile("ldmatrix.sync.aligned.m8n8.x4.shared.b16 {%0,%1,%2,%3}, [%4];"
        : "=r"(r[0]), "=r"(r[1]), "=r"(r[2]), "=r"(r[3]) : "r"(addr));
}

__device__ __forceinline__ void split2h(float x0, float x1,
                                        __half2& hi, __half2& lo) {
    hi = __floats2half2_rn(x0, x1);
    float2 hf = __half22float2(hi);
    lo = __floats2half2_rn(x0 - hf.x, x1 - hf.y);
}

__device__ __forceinline__ uint32_t h2u(__half2 v) {
    return *reinterpret_cast<uint32_t*>(&v);
}

// ---------------------------------------------------------------------------
// pre-pass: all fp32->fp16 conversions in ONE launch
// ---------------------------------------------------------------------------
#define SEG0 (2 * 1024 * 1024)
#define SEG1 (SEG0 + 4 * 1024 * 1024)
#define SEG2 (SEG1 + 1024 * 1024)
#define SEG3 (SEG2 + 1024 * 1024)
#define SEG4 (SEG3 + 4 * 1024 * 1024)

__global__ __launch_bounds__(256)
void split_all(const float4* __restrict__ hidden, const float4* __restrict__ Wq,
               const float4* __restrict__ Wk, const float4* __restrict__ Wv,
               const float4* __restrict__ Wo)
{
    int stride = gridDim.x * blockDim.x;
    for (int i = blockIdx.x * blockDim.x + threadIdx.x; i < SEG4; i += stride) {
        const float4* src;
        uint2* hi;
        int off;
        if (i < SEG0)      { src = hidden; off = i;        hi = (uint2*)g_hh; }
        else if (i < SEG1) { src = Wq;     off = i - SEG0; hi = (uint2*)g_wqh; }
        else if (i < SEG2) { src = Wk;     off = i - SEG1; hi = (uint2*)g_wkh; }
        else if (i < SEG3) { src = Wv;     off = i - SEG2; hi = (uint2*)g_wvh; }
        else               { src = Wo;     off = i - SEG3; hi = (uint2*)g_woh; }
        float4 v = src[off];
        hi[off] = make_uint2(h2u(__floats2half2_rn(v.x, v.y)),
                             h2u(__floats2half2_rn(v.z, v.w)));
    }
}

// ---------------------------------------------------------------------------
// fp16 1-term GEMM NT with cp.async, BK=64.
// CTA tile 128x128, 256 threads, 8 warps (4m x 2n), warp tile 32x64.
// Stage: A,B planes 128 rows x 72 halves (stride 72, ldsm conflict-free);
// 36864 B/stage, 3 stages = 110592 B -> 2 CTAs/SM. Barriers halved vs BK=32.
// MMA k-order identical to R16 -> bit-identical results.
// ---------------------------------------------------------------------------
#define LDB2   72
#define AP2_H  (128 * LDB2)              // 9216 halves per plane
#define STG2_B (2 * AP2_H * 2)           // 36864 B per stage
#define HGEMM_SMEM (3 * STG2_B)          // 110592 B

__device__ __forceinline__ void hgemm_body(const __half* __restrict__ Ah,
                                           const __half* __restrict__ Bh,
                                           float* __restrict__ C,
                                           int N, int K, int bx, int by)
{
    extern __shared__ char smc[];
    const uint32_t smem_u32 = (uint32_t)__cvta_generic_to_shared(smc);

    const int tid  = threadIdx.x;
    const int warp = tid >> 5;
    const int lane = tid & 31;
    const int g    = lane >> 2;
    const int t    = lane & 3;
    const int wm   = (warp & 3) * 32;
    const int wn   = (warp >> 2) * 64;

    // loader: 8 x 16B chunks per thread per stage.
    // j=0..3 -> A rows (tid>>3)+32j, j=4..7 -> B rows (tid>>3)+32(j-4);
    // col chunk = (tid&7)*8 halves. Single base pointer per matrix.
    const int lr = tid >> 3;            // 0..31
    const int lc = (tid & 7) * 8;       // halves
    const __half* srcA = Ah + (size_t)(by * 128 + lr) * K + lc;
    const __half* srcB = Bh + (size_t)(bx * 128 + lr) * K + lc;
    const uint32_t dstA = (uint32_t)(lr * LDB2 + lc) * 2;
    const uint32_t dstB = (uint32_t)(AP2_H + lr * LDB2 + lc) * 2;

    const int lane8 = lane & 7;
    const uint32_t a_off = (uint32_t)(((wm + lane8 + ((lane >> 3) & 1) * 8) * LDB2
                                      + (lane >> 4) * 8) * 2);
    const uint32_t b_off = (uint32_t)((AP2_H + (wn + lane8 + (lane >> 4) * 8) * LDB2
                                      + ((lane >> 3) & 1) * 8) * 2);

    float acc[2][8][4];
#pragma unroll
    for (int mt = 0; mt < 2; mt++)
#pragma unroll
        for (int nt = 0; nt < 8; nt++)
#pragma unroll
            for (int c = 0; c < 4; c++) acc[mt][nt][c] = 0.0f;

    const int nk = K / 64;

#define CP_ISSUE(KT)                                                           \
    {                                                                          \
        uint32_t sb_ = smem_u32 + (uint32_t)(((KT) % 3) * STG2_B);             \
        const __half* sA_ = srcA + (KT) * 64;                                  \
        const __half* sB_ = srcB + (KT) * 64;                                  \
        _Pragma("unroll")                                                      \
        for (int j = 0; j < 4; j++) {                                          \
            asm volatile("cp.async.cg.shared.global [%0], [%1], 16;"           \
                :: "r"(sb_ + dstA + (uint32_t)(j * 32 * LDB2 * 2)),            \
                   "l"(sA_ + (size_t)j * 32 * K) : "memory");                  \
            asm volatile("cp.async.cg.shared.global [%0], [%1], 16;"           \
                :: "r"(sb_ + dstB + (uint32_t)(j * 32 * LDB2 * 2)),            \
                   "l"(sB_ + (size_t)j * 32 * K) : "memory");                  \
        }                                                                      \
    }
#define CP_COMMIT() asm volatile("cp.async.commit_group;" ::: "memory")

    CP_ISSUE(0); CP_COMMIT();
    CP_ISSUE(1); CP_COMMIT();

    for (int kt = 0; kt < nk; kt++) {
        asm volatile("cp.async.wait_group 1;" ::: "memory");
        __syncthreads();
        if (kt + 2 < nk) { CP_ISSUE(kt + 2); }
        CP_COMMIT();

        const uint32_t sb = smem_u32 + (uint32_t)((kt % 3) * STG2_B);

#pragma unroll
        for (int k16 = 0; k16 < 4; k16++) {
            uint32_t ah[2][4];
            ldsm4(ah[0], sb + a_off + k16 * 32);
            ldsm4(ah[1], sb + a_off + 16 * LDB2 * 2 + k16 * 32);

#pragma unroll
            for (int jh = 0; jh < 2; jh++) {
                uint32_t bh[2][4];
#pragma unroll
                for (int jj = 0; jj < 2; jj++) {
                    int j = jh * 2 + jj;
                    ldsm4(bh[jj], sb + b_off + j * 16 * LDB2 * 2 + k16 * 32);
                }
#pragma unroll
                for (int mt = 0; mt < 2; mt++)
#pragma unroll
                    for (int jj = 0; jj < 2; jj++) {
                        int nt = (jh * 2 + jj) * 2;
                        mma_f16(acc[mt][nt], ah[mt][0], ah[mt][1], ah[mt][2],
                                ah[mt][3], bh[jj][0], bh[jj][1]);
                        mma_f16(acc[mt][nt + 1], ah[mt][0], ah[mt][1], ah[mt][2],
                                ah[mt][3], bh[jj][2], bh[jj][3]);
                    }
            }
        }
    }

#pragma unroll
    for (int mt = 0; mt < 2; mt++) {
        int r0 = by * 128 + wm + mt * 16 + g;
#pragma unroll
        for (int nt = 0; nt < 8; nt++) {
            int c0 = bx * 128 + wn + nt * 8 + 2 * t;
            *(float2*)&C[(size_t)r0 * N + c0] =
                make_float2(acc[mt][nt][0], acc[mt][nt][1]);
            *(float2*)&C[(size_t)(r0 + 8) * N + c0] =
                make_float2(acc[mt][nt][2], acc[mt][nt][3]);
        }
    }
#undef CP_ISSUE
#undef CP_COMMIT
}

__global__ __launch_bounds__(256, 2)
void hgemm_qkv()
{
    int b = blockIdx.x;
    if (b < 512)      hgemm_body(g_hh, g_wqh, g_q, 4096, 4096, b & 31, b >> 5);
    else if (b < 640) { int i = b - 512; hgemm_body(g_hh, g_wkh, g_k, 1024, 4096, i & 7, i >> 3); }
    else              { int i = b - 640; hgemm_body(g_hh, g_wvh, g_v, 1024, 4096, i & 7, i >> 3); }
}

__global__ __launch_bounds__(256, 2)
void hgemm_o(float* __restrict__ out)
{
    hgemm_body(g_ah, g_woh, out, 4096, 4096, blockIdx.x, blockIdx.y);
}

// ---------------------------------------------------------------------------
// Fused aux kernel (R16 verbatim): norm+rope blocks then vtrans blocks
// ---------------------------------------------------------------------------
#define NORM_BLOCKS 10240
#define AUX_BLOCKS  (NORM_BLOCKS + 2048)

__global__ __launch_bounds__(256)
void norm_rope_vtrans(const float* __restrict__ cosb,
                      const float* __restrict__ sinb,
                      const float* __restrict__ qw, const float* __restrict__ kw)
{
    if (blockIdx.x < NORM_BLOCKS) {
        const int warp = blockIdx.x * 8 + (threadIdx.x >> 5);
        const int lane = threadIdx.x & 31;

        const float* base;
        const float* w;
        int s;
        bool is_q = warp < S_LEN * NQH;
        size_t off;
        if (is_q) {
            s = warp / NQH;
            int h = warp - s * NQH;
            off = (size_t)s * D_MODEL + h * HD;
            base = g_q + off;
            w = qw;
        } else {
            int wv = warp - S_LEN * NQH;
            s = wv / NKVH;
            int h = wv - s * NKVH;
            off = (size_t)s * KV_DIM + h * HD;
            base = g_k + off;
            w = kw;
        }

        float x0 = base[lane];
        float x1 = base[lane + 32];
        float x2 = base[lane + 64];
        float x3 = base[lane + 96];

        float ss = x0 * x0 + x1 * x1 + x2 * x2 + x3 * x3;
#pragma unroll
        for (int o = 16; o; o >>= 1) ss += __shfl_xor_sync(0xffffffffu, ss, o);
        float inv = rsqrtf(ss * (1.0f / 128.0f) + 1e-6f);

        float n0 = w[lane]      * x0 * inv;
        float n1 = w[lane + 32] * x1 * inv;
        float n2 = w[lane + 64] * x2 * inv;
        float n3 = w[lane + 96] * x3 * inv;

        const float c0 = cosb[s * 64 + lane];
        const float c1 = cosb[s * 64 + lane + 32];
        const float s0 = sinb[s * 64 + lane];
        const float s1 = sinb[s * 64 + lane + 32];

        float r0 = n0 * c0 - n2 * s0;
        float r1 = n1 * c1 - n3 * s1;
        float r2 = n2 * c0 + n0 * s0;
        float r3 = n3 * c1 + n1 * s1;

        __half* dst = is_q ? g_qh : g_kh;
        dst[off + lane]      = __float2half_rn(r0);
        dst[off + lane + 32] = __float2half_rn(r1);
        dst[off + lane + 64] = __float2half_rn(r2);
        dst[off + lane + 96] = __float2half_rn(r3);
    } else {
        __shared__ float tile[32][33];
        int b = blockIdx.x - NORM_BLOCKS;
        const int kvh = b & 7;
        const int d0  = ((b >> 3) & 3) * 32;
        const int s0  = (b >> 5) * 32;
        const int tx = threadIdx.x & 31;
        const int ty = threadIdx.x >> 5;

#pragma unroll
        for (int i = 0; i < 4; i++) {
            int sl = ty + i * 8;
            tile[sl][tx] = g_v[(size_t)(s0 + sl) * KV_DIM + kvh * HD + d0 + tx];
        }
        __syncthreads();
#pragma unroll
        for (int i = 0; i < 4; i++) {
            int dl = ty + i * 8;
            g_vt[(size_t)(kvh * HD + d0 + dl) * S_LEN + s0 + tx] =
                __float2half_rn(tile[tx][dl]);
        }
    }
}

// ---------------------------------------------------------------------------
// Tensor-core flash attention (R13/R16 verbatim)
// ---------------------------------------------------------------------------
#define OFF_QH   0
#define OFF_FKV  17408
#define FKVBUF   17920
#define FLASH_SMEM_TC ((OFF_FKV + 4 * FKVBUF) * 2)   // 178176 B

__global__ __launch_bounds__(256, 1)
void flash_attn_tc()
{
    extern __shared__ __half smh[];

    const int qt  = 15 - blockIdx.x;
    const int h   = blockIdx.y;
    const int q0  = qt * 128;
    const int kvh = h >> 2;
    const int tid  = threadIdx.x;
    const int warp = tid >> 5;
    const int lane = tid & 31;
    const int g = lane >> 2;
    const int t = lane & 3;

    const uint32_t sbase = (uint32_t)__cvta_generic_to_shared(smh);

#define CP16(DST, SRC)                                                         \
    asm volatile("cp.async.cg.shared.global [%0], [%1], 16;"                   \
                 :: "r"(DST), "l"(SRC) : "memory")
#define CP_COMMIT() asm volatile("cp.async.commit_group;" ::: "memory")

#define LOAD_KV(KT, BUF)                                                       \
    {                                                                          \
        const uint32_t kb_ = sbase + (uint32_t)(OFF_FKV + (BUF) * FKVBUF) * 2; \
        const int k0_ = (KT) * 64;                                             \
        _Pragma("unroll")                                                      \
        for (int j = 0; j < 8; j++) {                                          \
            int cid = tid + j * 256;                                           \
            if (cid < 1024) {                                                  \
                int r = cid >> 4, c = cid & 15;                                \
                CP16(kb_ + (uint32_t)(r * 136 + c * 8) * 2,                    \
                     g_kh + (size_t)(k0_ + r) * KV_DIM + kvh * HD + c * 8);    \
            } else {                                                           \
                int b = cid - 1024;                                            \
                int r = b >> 3, c = b & 7;                                     \
                CP16(kb_ + (uint32_t)(8704 + r * 72 + c * 8) * 2,              \
                     g_vt + (size_t)(kvh * HD + r) * S_LEN + k0_ + c * 8);     \
            }                                                                  \
        }                                                                      \
    }

    const int wrow = q0 + warp * 16;
    const int nkt  = 2 * qt + 2;

#pragma unroll
    for (int j = 0; j < 8; j++) {
        int cid = tid + j * 256;
        int r = cid >> 4, c = cid & 15;
        CP16(sbase + (uint32_t)(OFF_QH + r * 136 + c * 8) * 2,
             g_qh + (size_t)(q0 + r) * D_MODEL + h * HD + c * 8);
    }
    LOAD_KV(0, 0);
    CP_COMMIT();
    if (1 < nkt) LOAD_KV(1, 1);
    CP_COMMIT();
    if (2 < nkt) LOAD_KV(2, 2);
    CP_COMMIT();

    float o[16][4];
#pragma unroll
    for (int nt = 0; nt < 16; nt++)
#pragma unroll
        for (int j = 0; j < 4; j++) o[nt][j] = 0.0f;
    float m0 = -1e30f, m1 = -1e30f, l0 = 0.0f, l1 = 0.0f;

    const __half* qrh = smh + OFF_QH + (warp * 16 + g) * 136 + 2 * t;

    for (int kt = 0; kt < nkt; kt++) {
        const int k0 = kt * 64;
        asm volatile("cp.async.wait_group 2;" ::: "memory");
        __syncthreads();
        if (kt + 3 < nkt) LOAD_KV(kt + 3, (kt + 3) & 3);
        CP_COMMIT();

        if (k0 > wrow + 15) continue;

        const __half* Kh = smh + OFF_FKV + (kt & 3) * FKVBUF;
        const __half* Vh = Kh + 8704;

        float s[8][4];
#pragma unroll
        for (int nt = 0; nt < 8; nt++)
#pragma unroll
            for (int j = 0; j < 4; j++) s[nt][j] = 0.0f;

#pragma unroll
        for (int c = 0; c < 8; c++) {
            uint32_t ah0 = *(const uint32_t*)(qrh + c * 16);
            uint32_t ah1 = *(const uint32_t*)(qrh + 8 * 136 + c * 16);
            uint32_t ah2 = *(const uint32_t*)(qrh + c * 16 + 8);
            uint32_t ah3 = *(const uint32_t*)(qrh + 8 * 136 + c * 16 + 8);
#pragma unroll
            for (int nt = 0; nt < 8; nt++) {
                const __half* kp = Kh + (nt * 8 + g) * 136 + c * 16 + 2 * t;
                uint32_t b0 = *(const uint32_t*)(kp);
                uint32_t b1 = *(const uint32_t*)(kp + 8);
                mma_f16(s[nt], ah0, ah1, ah2, ah3, b0, b1);
            }
        }

        if (k0 + 63 > wrow) {
            int r0 = wrow + g, r1 = r0 + 8;
#pragma unroll
            for (int nt = 0; nt < 8; nt++) {
                int c0 = k0 + nt * 8 + 2 * t;
                s[nt][0] = (c0     > r0) ? -1e30f : s[nt][0] * SCALE_F;
                s[nt][1] = (c0 + 1 > r0) ? -1e30f : s[nt][1] * SCALE_F;
                s[nt][2] = (c0     > r1) ? -1e30f : s[nt][2] * SCALE_F;
                s[nt][3] = (c0 + 1 > r1) ? -1e30f : s[nt][3] * SCALE_F;
            }
        } else {
#pragma unroll
            for (int nt = 0; nt < 8; nt++)
#pragma unroll
                for (int j = 0; j < 4; j++) s[nt][j] *= SCALE_F;
        }

        float mx0 = -1e30f, mx1 = -1e30f;
#pragma unroll
        for (int nt = 0; nt < 8; nt++) {
            mx0 = fmaxf(mx0, fmaxf(s[nt][0], s[nt][1]));
            mx1 = fmaxf(mx1, fmaxf(s[nt][2], s[nt][3]));
        }
        mx0 = fmaxf(mx0, __shfl_xor_sync(0xffffffffu, mx0, 1));
        mx0 = fmaxf(mx0, __shfl_xor_sync(0xffffffffu, mx0, 2));
        mx1 = fmaxf(mx1, __shfl_xor_sync(0xffffffffu, mx1, 1));
        mx1 = fmaxf(mx1, __shfl_xor_sync(0xffffffffu, mx1, 2));

        float mn0 = fmaxf(m0, mx0), mn1 = fmaxf(m1, mx1);
        float a0 = __expf(m0 - mn0), a1 = __expf(m1 - mn1);
        m0 = mn0; m1 = mn1;

        float sum0 = 0.0f, sum1 = 0.0f;
#pragma unroll
        for (int nt = 0; nt < 8; nt++) {
            s[nt][0] = __expf(s[nt][0] - m0);
            s[nt][1] = __expf(s[nt][1] - m0);
            s[nt][2] = __expf(s[nt][2] - m1);
            s[nt][3] = __expf(s[nt][3] - m1);
            sum0 += s[nt][0] + s[nt][1];
            sum1 += s[nt][2] + s[nt][3];
        }
        sum0 += __shfl_xor_sync(0xffffffffu, sum0, 1);
        sum0 += __shfl_xor_sync(0xffffffffu, sum0, 2);
        sum1 += __shfl_xor_sync(0xffffffffu, sum1, 1);
        sum1 += __shfl_xor_sync(0xffffffffu, sum1, 2);
        l0 = l0 * a0 + sum0;
        l1 = l1 * a1 + sum1;

#pragma unroll
        for (int nt = 0; nt < 16; nt++) {
            o[nt][0] *= a0; o[nt][1] *= a0;
            o[nt][2] *= a1; o[nt][3] *= a1;
        }

#pragma unroll
        for (int c = 0; c < 4; c++) {
            __half2 h0, lo0, h1, lo1, h2, lo2, h3, lo3;
            split2h(s[2 * c][0],     s[2 * c][1],     h0, lo0);
            split2h(s[2 * c][2],     s[2 * c][3],     h1, lo1);
            split2h(s[2 * c + 1][0], s[2 * c + 1][1], h2, lo2);
            split2h(s[2 * c + 1][2], s[2 * c + 1][3], h3, lo3);
            uint32_t ph0 = h2u(h0), ph1 = h2u(h1), ph2 = h2u(h2), ph3 = h2u(h3);
            uint32_t pl0 = h2u(lo0), pl1 = h2u(lo1), pl2 = h2u(lo2), pl3 = h2u(lo3);
#pragma unroll
            for (int nt = 0; nt < 16; nt++) {
                const __half* vp = Vh + (nt * 8 + g) * 72 + c * 16 + 2 * t;
                uint32_t vh0 = *(const uint32_t*)(vp);
                uint32_t vh1 = *(const uint32_t*)(vp + 8);
                mma_f16(o[nt], ph0, ph1, ph2, ph3, vh0, vh1);
                mma_f16(o[nt], pl0, pl1, pl2, pl3, vh0, vh1);
            }
        }
    }

    float inv0 = 1.0f / l0, inv1 = 1.0f / l1;
    int row0 = q0 + warp * 16 + g;
#pragma unroll
    for (int nt = 0; nt < 16; nt++) {
        int col = h * HD + nt * 8 + 2 * t;
        *(uint32_t*)&g_ah[(size_t)row0 * D_MODEL + col] =
            h2u(__floats2half2_rn(o[nt][0] * inv0, o[nt][1] * inv0));
        *(uint32_t*)&g_ah[(size_t)(row0 + 8) * D_MODEL + col] =
            h2u(__floats2half2_rn(o[nt][2] * inv1, o[nt][3] * inv1));
    }
#undef LOAD_KV
#undef CP16
#undef CP_COMMIT
}

// ---------------------------------------------------------------------------
extern "C" void kernel_launch(void* const* d_in, const int* in_sizes, int n_in,
                              void* d_out, int out_size)
{
    const float* hidden = (const float*)d_in[0];
    const float* cosb   = (const float*)d_in[1];
    const float* sinb   = (const float*)d_in[2];
    const float* Wq = (const float*)d_in[4];
    const float* Wk = (const float*)d_in[5];
    const float* Wv = (const float*)d_in[6];
    const float* Wo = (const float*)d_in[7];
    const float* qw = (const float*)d_in[8];
    const float* kw = (const float*)d_in[9];
    float* out = (float*)d_out;

    cudaFuncSetAttribute(hgemm_qkv, cudaFuncAttributeMaxDynamicSharedMemorySize, HGEMM_SMEM);
    cudaFuncSetAttribute(hgemm_o,   cudaFuncAttributeMaxDynamicSharedMemorySize, HGEMM_SMEM);
    cudaFuncSetAttribute(flash_attn_tc, cudaFuncAttributeMaxDynamicSharedMemorySize, FLASH_SMEM_TC);

    split_all<<<2048, 256>>>((const float4*)hidden, (const float4*)Wq,
                             (const float4*)Wk, (const float4*)Wv,
                             (const float4*)Wo);

    hgemm_qkv<<<768, 256, HGEMM_SMEM>>>();

    norm_rope_vtrans<<<AUX_BLOCKS, 256>>>(cosb, sinb, qw, kw);

    flash_attn_tc<<<dim3(16, 32), 256, FLASH_SMEM_TC>>>();

    hgemm_o<<<dim3(32, 16), 256, HGEMM_SMEM>>>(out);
}